// round 13
// baseline (speedup 1.0000x reference)
#include <cuda_runtime.h>
#include <math.h>
#include <stdint.h>

// Problem constants
#define BB   16
#define SS   512
#define NCH  321
#define DD   512
#define DFF  2048
#define PP   96
#define BN   (BB*NCH)          // 5136 tokens

// ---------------------------------------------------------------------------
// Scratch buffers
// ---------------------------------------------------------------------------
__device__ float g_means[BN];
__device__ float g_stdev[BN];
__device__ float g_xn    [(size_t)BN*SS];
__device__ float g_h     [(size_t)BN*DD];
__device__ float g_coeffs[(size_t)BN*4*DD];
__device__ float g_q     [(size_t)BN*4*DD];
__device__ float g_k     [(size_t)BN*4*DD];
__device__ float g_v     [(size_t)BN*4*DD];
__device__ float g_qn2   [BB*4*DD];
__device__ float g_kn2   [BB*4*DD];
__device__ float g_sc    [(size_t)BB*4*DD*DD];   // 64 x 512 x 512
__device__ float g_smax  [BB*4*DD];
__device__ float g_sinv  [BB*4*DD];
__device__ float g_attn  [(size_t)BN*4*DD];
__device__ float g_rec   [(size_t)BN*DD];
__device__ float g_o     [(size_t)BN*DD];
__device__ float g_x1    [(size_t)BN*DD];
__device__ float g_y     [(size_t)BN*DFF];
__device__ float g_z     [(size_t)BN*DD];
__device__ float g_hf    [(size_t)BN*DD];
__device__ float g_dec   [(size_t)BN*PP];

// ---------------------------------------------------------------------------
// Helpers
// ---------------------------------------------------------------------------
__device__ __forceinline__ uint32_t f2tf(float x) {
    uint32_t r;
    asm("cvt.rna.tf32.f32 %0, %1;" : "=r"(r) : "f"(x));
    return r;
}

#define MMA8(cc, A0, A1, A2, A3, B0, B1)                                     \
    asm volatile("mma.sync.aligned.m16n8k8.row.col.f32.tf32.tf32.f32 "      \
        "{%0,%1,%2,%3}, {%4,%5,%6,%7}, {%8,%9}, {%0,%1,%2,%3};"             \
        : "+f"(cc[0]), "+f"(cc[1]), "+f"(cc[2]), "+f"(cc[3])                \
        : "r"(A0), "r"(A1), "r"(A2), "r"(A3), "r"(B0), "r"(B1))

__device__ __forceinline__ float blk_sum(float v, float* sh) {
    #pragma unroll
    for (int o = 16; o; o >>= 1) v += __shfl_xor_sync(0xffffffffu, v, o);
    int t = threadIdx.x;
    if ((t & 31) == 0) sh[t >> 5] = v;
    __syncthreads();
    v = sh[0] + sh[1] + sh[2] + sh[3] + sh[4] + sh[5] + sh[6] + sh[7];
    __syncthreads();
    return v;
}

// ---------------------------------------------------------------------------
// TF32 tensor-core GEMM tile: 128x128 CTA, BK=16, 8 warps (2x4), warp 64x32.
// Depth-2 register prefetch: while computing k-stage i, the global loads for
// stage i+2 are in flight and stage i+1 is staged from registers to smem.
// Smem k-permuted: col = (k&3)*4 + (k>>2), row pad 20 words -> LDS.128 frags.
// LAYOUT 0 (NT): C[m,n] = sum_k A[m*lda+k] * B[n*ldb+k]   (K % 16 == 0)
// LAYOUT 1 (TN): C[m,n] = sum_k A[k*lda+m] * B[k*ldb+n]   (arbitrary K)
// EPI 0: +bias    EPI 1: +bias, exact GELU    EPI 2: geometric wedge score
// SOFTB: B rows are attention scores; apply exp(x - smax[row]) * sinv[row]
// ---------------------------------------------------------------------------
template<int LAYOUT, int EPI, bool SOFTB = false>
__device__ __forceinline__ void mma_tile(
    const float* __restrict__ A, const float* __restrict__ Bm,
    const float* __restrict__ bias, float* __restrict__ C,
    int M, int N, int K, int lda, int ldb, int ldc,
    const float* __restrict__ rown, const float* __restrict__ coln,
    const float* __restrict__ smax = nullptr, const float* __restrict__ sinv = nullptr)
{
    constexpr int BKP = 20;
    __shared__ uint32_t As[2][128 * BKP];
    __shared__ uint32_t Bs[2][128 * BKP];

    const int tid  = threadIdx.x;
    const int lane = tid & 31;
    const int g    = lane >> 2;
    const int t    = lane & 3;
    const int wid  = tid >> 5;
    const int wm   = (wid >> 2) * 64;
    const int wn   = (wid & 3) * 32;
    const int m0   = blockIdx.y * 128;
    const int n0   = blockIdx.x * 128;

    float c[4][4][4];
    #pragma unroll
    for (int i = 0; i < 4; i++)
        #pragma unroll
        for (int j = 0; j < 4; j++)
            #pragma unroll
            for (int r = 0; r < 4; r++) c[i][j][r] = 0.f;

    // loader indices
    const int r_nt  = tid >> 1;          // 0..127
    const int kg_nt = (tid & 1) * 8;     // 0 or 8
    const int kr_tn = tid >> 4;          // 0..15
    const int mc_tn = (tid & 15) * 8;    // 0..120
    const bool aok = (m0 + ((LAYOUT == 0) ? r_nt : mc_tn)) < M;
    const bool bok = (n0 + ((LAYOUT == 0) ? r_nt : mc_tn)) < N;

    float mxv = 0.f, invv = 1.f;
    if (SOFTB) {
        const int rr = n0 + r_nt;
        if (rr < N) { mxv = smax[rr]; invv = sinv[rr]; }
    }
    #define XB(x) (SOFTB ? expf((x) - mxv) * invv : (x))

    float va0[8], vb0[8], va1[8], vb1[8];

    #define FETCH(k0, VA, VB)                                                 \
        {                                                                     \
            _Pragma("unroll")                                                 \
            for (int j = 0; j < 8; j++) { VA[j] = 0.f; VB[j] = 0.f; }         \
            if (LAYOUT == 0) {                                                \
                if (aok) {                                                    \
                    const float4* p = (const float4*)(A + (size_t)(m0 + r_nt) * lda + (k0) + kg_nt); \
                    float4 x0 = p[0], x1 = p[1];                              \
                    VA[0]=x0.x; VA[1]=x0.y; VA[2]=x0.z; VA[3]=x0.w;           \
                    VA[4]=x1.x; VA[5]=x1.y; VA[6]=x1.z; VA[7]=x1.w;           \
                }                                                             \
                if (bok) {                                                    \
                    const float4* p = (const float4*)(Bm + (size_t)(n0 + r_nt) * ldb + (k0) + kg_nt); \
                    float4 x0 = p[0], x1 = p[1];                              \
                    VB[0]=x0.x; VB[1]=x0.y; VB[2]=x0.z; VB[3]=x0.w;           \
                    VB[4]=x1.x; VB[5]=x1.y; VB[6]=x1.z; VB[7]=x1.w;           \
                }                                                             \
            } else {                                                          \
                const int gk = (k0) + kr_tn;                                  \
                if (gk < K) {                                                 \
                    if (aok) {                                                \
                        const float4* pa = (const float4*)(A + (size_t)gk * lda + m0 + mc_tn); \
                        float4 x0 = pa[0], x1 = pa[1];                        \
                        VA[0]=x0.x; VA[1]=x0.y; VA[2]=x0.z; VA[3]=x0.w;       \
                        VA[4]=x1.x; VA[5]=x1.y; VA[6]=x1.z; VA[7]=x1.w;       \
                    }                                                         \
                    if (bok) {                                                \
                        const float4* pb = (const float4*)(Bm + (size_t)gk * ldb + n0 + mc_tn); \
                        float4 y0 = pb[0], y1 = pb[1];                        \
                        VB[0]=y0.x; VB[1]=y0.y; VB[2]=y0.z; VB[3]=y0.w;       \
                        VB[4]=y1.x; VB[5]=y1.y; VB[6]=y1.z; VB[7]=y1.w;       \
                    }                                                         \
                }                                                             \
            }                                                                 \
        }

    #define STAGE(VA, VB, bf)                                                \
        {                                                                     \
            if (LAYOUT == 0) {                                                \
                const int cb = kg_nt >> 2;      /* 0 or 2 */                  \
                _Pragma("unroll")                                             \
                for (int j = 0; j < 4; j++) {                                 \
                    uint2 pa = make_uint2(f2tf(VA[j]), f2tf(VA[j+4]));        \
                    *(uint2*)&As[bf][r_nt * BKP + 4*j + cb] = pa;             \
                    uint2 pb = make_uint2(f2tf(XB(VB[j])), f2tf(XB(VB[j+4])));\
                    *(uint2*)&Bs[bf][r_nt * BKP + 4*j + cb] = pb;             \
                }                                                             \
            } else {                                                          \
                const int p = (kr_tn & 3) * 4 + (kr_tn >> 2);                 \
                _Pragma("unroll")                                             \
                for (int j = 0; j < 8; j++) {                                 \
                    As[bf][(mc_tn + j) * BKP + p] = f2tf(VA[j]);              \
                    Bs[bf][(mc_tn + j) * BKP + p] = f2tf(VB[j]);              \
                }                                                             \
            }                                                                 \
        }

    #define COMPUTE(bf)                                                      \
        {                                                                     \
            uint32_t bfr[4][4];                                               \
            _Pragma("unroll")                                                 \
            for (int j = 0; j < 4; j++)                                       \
                *(uint4*)bfr[j] = *(const uint4*)&Bs[bf][(wn + j * 8 + g) * BKP + 4 * t]; \
            _Pragma("unroll")                                                 \
            for (int i = 0; i < 4; i++) {                                     \
                uint32_t a0[4], a1[4];                                        \
                *(uint4*)a0 = *(const uint4*)&As[bf][(wm + i * 16 + g)     * BKP + 4 * t]; \
                *(uint4*)a1 = *(const uint4*)&As[bf][(wm + i * 16 + 8 + g) * BKP + 4 * t]; \
                _Pragma("unroll")                                             \
                for (int j = 0; j < 4; j++) {                                 \
                    MMA8(c[i][j], a0[0], a1[0], a0[1], a1[1], bfr[j][0], bfr[j][1]); \
                    MMA8(c[i][j], a0[2], a1[2], a0[3], a1[3], bfr[j][2], bfr[j][3]); \
                }                                                             \
            }                                                                 \
        }

    const int Kt = (LAYOUT == 0) ? K : ((K + 15) & ~15);
    const int S  = Kt >> 4;            // total k16 stages (>= 2 at all sites)
    const int T  = S - 2;              // main-loop iterations

    FETCH(0, va0, vb0);
    STAGE(va0, vb0, 0);
    FETCH(16, va1, vb1);
    __syncthreads();

    int buf = 0;
    int k2  = 32;
    for (int it = 0; it + 2 <= T; it += 2) {
        FETCH(k2, va0, vb0); k2 += 16;
        COMPUTE(buf);
        STAGE(va1, vb1, buf ^ 1);
        __syncthreads();
        buf ^= 1;
        FETCH(k2, va1, vb1); k2 += 16;
        COMPUTE(buf);
        STAGE(va0, vb0, buf ^ 1);
        __syncthreads();
        buf ^= 1;
    }
    if (T & 1) {
        FETCH(k2, va0, vb0);
        COMPUTE(buf);
        STAGE(va1, vb1, buf ^ 1);
        __syncthreads();
        buf ^= 1;
        COMPUTE(buf);
        STAGE(va0, vb0, buf ^ 1);
        __syncthreads();
        buf ^= 1;
        COMPUTE(buf);
    } else {
        COMPUTE(buf);
        STAGE(va1, vb1, buf ^ 1);
        __syncthreads();
        buf ^= 1;
        COMPUTE(buf);
    }

    #undef FETCH
    #undef STAGE
    #undef COMPUTE
    #undef XB

    // Epilogue
    const float scale = rsqrtf(321.0f);
    #pragma unroll
    for (int i = 0; i < 4; i++) {
        #pragma unroll
        for (int h = 0; h < 2; h++) {
            const int gm = m0 + wm + i * 16 + g + h * 8;
            if (gm >= M) continue;
            const float rn = (EPI == 2) ? rown[gm] : 0.f;
            #pragma unroll
            for (int j = 0; j < 4; j++) {
                const int gn = n0 + wn + j * 8 + 2 * t;
                float v0 = c[i][j][h * 2 + 0];
                float v1 = c[i][j][h * 2 + 1];
                if (EPI <= 1 && bias) {
                    if (gn     < N) v0 += bias[gn];
                    if (gn + 1 < N) v1 += bias[gn + 1];
                }
                if (EPI == 1) {
                    v0 = 0.5f * v0 * (1.f + erff(v0 * 0.70710678118654752f));
                    v1 = 0.5f * v1 * (1.f + erff(v1 * 0.70710678118654752f));
                }
                if (EPI == 2) {
                    float cn0 = (gn     < N) ? coln[gn]     : 0.f;
                    float cn1 = (gn + 1 < N) ? coln[gn + 1] : 0.f;
                    float w0 = sqrtf(fmaxf(rn * cn0 - v0 * v0, 0.f) + 1e-8f);
                    float w1 = sqrtf(fmaxf(rn * cn1 - v1 * v1, 0.f) + 1e-8f);
                    v0 = (0.7f * v0 + 0.3f * w0) * scale;
                    v1 = (0.7f * v1 + 0.3f * w1) * scale;
                }
                float* p = C + (size_t)gm * ldc + gn;
                if (gn + 1 < N)      *(float2*)p = make_float2(v0, v1);
                else if (gn < N)     *p = v0;
            }
        }
    }
}

__global__ void __launch_bounds__(256, 2) k_mma(
    const float* __restrict__ A, const float* __restrict__ B,
    const float* __restrict__ bias, float* __restrict__ C, int M, int N, int K)
{
    mma_tile<0, 0>(A, B, bias, C, M, N, K, K, K, N, nullptr, nullptr);
}
__global__ void __launch_bounds__(256, 2) k_mma_gelu(
    const float* __restrict__ A, const float* __restrict__ B,
    const float* __restrict__ bias, float* __restrict__ C, int M, int N, int K)
{
    mma_tile<0, 1>(A, B, bias, C, M, N, K, K, K, N, nullptr, nullptr);
}

// Fused Q/K/V projection (blockIdx.z selects the projection)
__global__ void __launch_bounds__(256, 2) k_qkv(
    const float* __restrict__ coeffs,
    const float* __restrict__ Wq, const float* __restrict__ Wk, const float* __restrict__ Wv,
    const float* __restrict__ bq, const float* __restrict__ bk, const float* __restrict__ bv,
    float* __restrict__ q, float* __restrict__ k, float* __restrict__ v)
{
    const float* W; const float* bi; float* out;
    if (blockIdx.z == 0)      { W = Wq; bi = bq; out = q; }
    else if (blockIdx.z == 1) { W = Wk; bi = bk; out = k; }
    else                      { W = Wv; bi = bv; out = v; }
    mma_tile<0, 0>(coeffs, W, bi, out, BN * 4, DD, DD, DD, DD, DD, nullptr, nullptr);
}

// dot + geometric score, batched over z = b*4 + head (TN over channels)
__global__ void __launch_bounds__(256, 2) k_dot_geom(
    const float* __restrict__ q, const float* __restrict__ k,
    const float* __restrict__ qn2, const float* __restrict__ kn2,
    float* __restrict__ sc)
{
    const int z = blockIdx.z;
    const int b = z >> 2, m = z & 3;
    const float* A  = q + (size_t)b * NCH * 2048 + m * 512;
    const float* Bm = k + (size_t)b * NCH * 2048 + m * 512;
    float* C = sc + (size_t)z * DD * DD;
    mma_tile<1, 2>(A, Bm, nullptr, C, DD, DD, NCH, 2048, 2048, DD,
                   qn2 + z * DD, kn2 + z * DD);
}

// attn out: C[d, l] = sum_s V[d,s] * P[l,s]; softmax applied on the fly to P
__global__ void __launch_bounds__(256, 2) k_av(
    const float* __restrict__ v, const float* __restrict__ pr,
    const float* __restrict__ smax, const float* __restrict__ sinv,
    float* __restrict__ attn)
{
    const int z = blockIdx.z;
    const int b = z >> 2, m = z & 3;
    const float* A  = v  + (size_t)b * NCH * 2048 + m * 512;
    const float* Bm = pr + (size_t)z * DD * DD;
    float* C = attn + (size_t)b * NCH * 2048 + m * 512;
    mma_tile<0, 0, true>(A, Bm, nullptr, C, NCH, DD, DD, 2048, DD, 2048,
                         nullptr, nullptr, smax + (size_t)z * DD, sinv + (size_t)z * DD);
}

// Per-row max and 1/sum(exp) over 512 score columns (one warp per row)
__global__ void __launch_bounds__(256) k_rowstats(
    const float* __restrict__ sc, float* __restrict__ smax, float* __restrict__ sinv)
{
    const int row  = blockIdx.x * 8 + (threadIdx.x >> 5);
    const int lane = threadIdx.x & 31;
    const float* p = sc + (size_t)row * DD;
    float v[16];
    float mx = -1e30f;
    #pragma unroll
    for (int i = 0; i < 16; i++) { v[i] = p[lane + 32 * i]; mx = fmaxf(mx, v[i]); }
    #pragma unroll
    for (int o = 16; o; o >>= 1) mx = fmaxf(mx, __shfl_xor_sync(0xffffffffu, mx, o));
    float s = 0.f;
    #pragma unroll
    for (int i = 0; i < 16; i++) s += expf(v[i] - mx);
    #pragma unroll
    for (int o = 16; o; o >>= 1) s += __shfl_xor_sync(0xffffffffu, s, o);
    if (lane == 0) { smax[row] = mx; sinv[row] = 1.f / s; }
}

// ---------------------------------------------------------------------------
// Input stats: means/stdev over S per (b, n)
// ---------------------------------------------------------------------------
__global__ void k_stats(const float* __restrict__ x,
                        float* __restrict__ means, float* __restrict__ stdev)
{
    const int b = blockIdx.x;
    const int n = blockIdx.y * 32 + threadIdx.x;
    float s = 0.f, s2 = 0.f;
    if (n < NCH) {
        for (int t = threadIdx.y; t < SS; t += 8) {
            float vv = x[((size_t)b * SS + t) * NCH + n];
            s += vv; s2 = fmaf(vv, vv, s2);
        }
    }
    __shared__ float sh[8][32], sh2[8][32];
    sh [threadIdx.y][threadIdx.x] = s;
    sh2[threadIdx.y][threadIdx.x] = s2;
    __syncthreads();
    if (threadIdx.y == 0 && n < NCH) {
        float a = 0.f, a2 = 0.f;
        #pragma unroll
        for (int i = 0; i < 8; i++) { a += sh[i][threadIdx.x]; a2 += sh2[i][threadIdx.x]; }
        float mu  = a * (1.f / SS);
        float var = a2 * (1.f / SS) - mu * mu;
        means[b * NCH + n] = mu;
        stdev[b * NCH + n] = sqrtf(var + 1e-5f);
    }
}

// Normalize + transpose: xn[b, n, s] = (x[b, s, n] - mu) / sd
__global__ void k_normT(const float* __restrict__ x,
                        const float* __restrict__ means, const float* __restrict__ stdev,
                        float* __restrict__ xn)
{
    __shared__ float tile[32][33];
    const int b  = blockIdx.z;
    const int s0 = blockIdx.x * 32;
    const int n0 = blockIdx.y * 32;
    #pragma unroll
    for (int r = 0; r < 4; r++) {
        int ss = s0 + threadIdx.y + r * 8;
        int nn = n0 + threadIdx.x;
        tile[threadIdx.y + r * 8][threadIdx.x] =
            (nn < NCH) ? x[((size_t)b * SS + ss) * NCH + nn] : 0.f;
    }
    __syncthreads();
    #pragma unroll
    for (int r = 0; r < 4; r++) {
        int nn = n0 + threadIdx.y + r * 8;
        int ss = s0 + threadIdx.x;
        if (nn < NCH) {
            float mu = means[b * NCH + nn];
            float sd = stdev[b * NCH + nn];
            xn[((size_t)b * NCH + nn) * SS + ss] =
                (tile[threadIdx.x][threadIdx.y + r * 8] - mu) / sd;
        }
    }
}

// ---------------------------------------------------------------------------
// SWT decomposition / reconstruction
// ---------------------------------------------------------------------------
__global__ void __launch_bounds__(512) k_swt_dec(
    const float* __restrict__ h, const float* __restrict__ h0,
    const float* __restrict__ h1, float* __restrict__ coeffs)
{
    const int bn = blockIdx.x;
    const int n  = bn % NCH;
    const int d  = threadIdx.x;
    __shared__ float buf[2][DD];
    buf[0][d] = h[(size_t)bn * DD + d];
    float f0[3], f1[3];
    #pragma unroll
    for (int kk = 0; kk < 3; kk++) { f0[kk] = h0[n * 3 + kk]; f1[kk] = h1[n * 3 + kk]; }
    __syncthreads();
    int cur = 0, dil = 1;
    const int pl[3] = {1, 1, 2};
    #pragma unroll
    for (int m = 0; m < 3; m++) {
        float det = 0.f, app = 0.f;
        #pragma unroll
        for (int kk = 0; kk < 3; kk++) {
            int idx = (d + kk * dil - pl[m] + DD) & (DD - 1);
            float vv = buf[cur][idx];
            det = fmaf(f1[kk], vv, det);
            app = fmaf(f0[kk], vv, app);
        }
        coeffs[((size_t)bn * 4 + (3 - m)) * DD + d] = det;
        buf[cur ^ 1][d] = app;
        __syncthreads();
        cur ^= 1; dil <<= 1;
    }
    coeffs[(size_t)bn * 4 * DD + d] = buf[cur][d];
}

__global__ void __launch_bounds__(512) k_swt_rec(
    const float* __restrict__ c, const float* __restrict__ g0,
    const float* __restrict__ g1, float* __restrict__ rec)
{
    const int bn = blockIdx.x;
    const int n  = bn % NCH;
    const int d  = threadIdx.x;
    __shared__ float app[2][DD];
    __shared__ float det[DD];
    app[0][d] = c[(size_t)bn * 4 * DD + d];
    float f0[3], f1[3];
    #pragma unroll
    for (int kk = 0; kk < 3; kk++) { f0[kk] = g0[n * 3 + kk]; f1[kk] = g1[n * 3 + kk]; }
    int cur = 0, dil = 4;
    const int pl[3] = {6, 3, 1};
    #pragma unroll
    for (int i = 0; i < 3; i++) {
        det[d] = c[((size_t)bn * 4 + 1 + i) * DD + d];
        __syncthreads();
        float acc = 0.f;
        #pragma unroll
        for (int kk = 0; kk < 3; kk++) {
            int idx = (d + kk * dil - pl[i] + DD) & (DD - 1);
            acc = fmaf(f0[kk], app[cur][idx], acc);
            acc = fmaf(f1[kk], det[idx], acc);
        }
        app[cur ^ 1][d] = 0.5f * acc;
        __syncthreads();
        cur ^= 1; dil >>= 1;
    }
    rec[(size_t)bn * DD + d] = app[cur][d];
}

// Row norms of Q and K over channels, per (b, head, l)
__global__ void __launch_bounds__(256) k_qknorms(
    const float* __restrict__ q, const float* __restrict__ k,
    float* __restrict__ qn2, float* __restrict__ kn2)
{
    const int z = blockIdx.y;
    const int b = z >> 2, m = z & 3;
    const int l = blockIdx.x * 256 + threadIdx.x;
    const size_t base = (size_t)b * NCH * 2048 + m * 512 + l;
    float sq = 0.f, sk = 0.f;
    for (int j = 0; j < NCH; j++) {
        float a = q[base + (size_t)j * 2048]; sq = fmaf(a, a, sq);
        float c = k[base + (size_t)j * 2048]; sk = fmaf(c, c, sk);
    }
    qn2[z * DD + l] = sq;
    kn2[z * DD + l] = sk;
}

// LayerNorm over D=512 (optionally fused residual add)
__global__ void __launch_bounds__(256) k_ln(
    const float* __restrict__ x, const float* __restrict__ res,
    const float* __restrict__ g, const float* __restrict__ bt,
    float* __restrict__ out)
{
    const size_t base = (size_t)blockIdx.x * DD;
    const int t = threadIdx.x;
    __shared__ float sh[8];
    float v0 = x[base + t], v1 = x[base + t + 256];
    if (res) { v0 += res[base + t]; v1 += res[base + t + 256]; }
    float s = blk_sum(v0 + v1, sh);
    float mu = s * (1.f / DD);
    float d0 = v0 - mu, d1 = v1 - mu;
    float vs = blk_sum(d0 * d0 + d1 * d1, sh);
    float rs = rsqrtf(vs * (1.f / DD) + 1e-5f);
    out[base + t]       = d0 * rs * g[t]       + bt[t];
    out[base + t + 256] = d1 * rs * g[t + 256] + bt[t + 256];
}

// dec output: out[b, p, n] = dec[b, n, p] * stdev[b, n] + means[b, n]
__global__ void k_dec_out(const float* __restrict__ dec,
                          const float* __restrict__ means, const float* __restrict__ stdev,
                          float* __restrict__ out)
{
    const int idx = blockIdx.x * 256 + threadIdx.x;
    if (idx >= BB * PP * NCH) return;
    const int n = idx % NCH;
    const int p = (idx / NCH) % PP;
    const int b = idx / (NCH * PP);
    out[idx] = dec[((size_t)b * NCH + n) * PP + p] * stdev[b * NCH + n] + means[b * NCH + n];
}

__global__ void k_tail(const float* __restrict__ means, const float* __restrict__ stdev,
                       float* __restrict__ out)
{
    const int i = blockIdx.x * 256 + threadIdx.x;
    if (i < BN) { out[i] = means[i]; out[BN + i] = stdev[i]; }
}

// ---------------------------------------------------------------------------
// Launch
// ---------------------------------------------------------------------------
extern "C" void kernel_launch(void* const* d_in, const int* in_sizes, int n_in,
                              void* d_out, int out_size)
{
    const float* x_enc  = (const float*)d_in[0];
    const float* emb_W  = (const float*)d_in[1];
    const float* emb_b  = (const float*)d_in[2];
    const float* h0     = (const float*)d_in[3];
    const float* h1     = (const float*)d_in[4];
    const float* g0     = (const float*)d_in[5];
    const float* g1     = (const float*)d_in[6];
    const float* Wq     = (const float*)d_in[7];
    const float* bq     = (const float*)d_in[8];
    const float* Wk     = (const float*)d_in[9];
    const float* bk     = (const float*)d_in[10];
    const float* Wv     = (const float*)d_in[11];
    const float* bv     = (const float*)d_in[12];
    const float* Wo     = (const float*)d_in[13];
    const float* bo     = (const float*)d_in[14];
    const float* W1     = (const float*)d_in[15];
    const float* b1     = (const float*)d_in[16];
    const float* W2     = (const float*)d_in[17];
    const float* b2     = (const float*)d_in[18];
    const float* ln1_g  = (const float*)d_in[19];
    const float* ln1_b  = (const float*)d_in[20];
    const float* ln2_g  = (const float*)d_in[21];
    const float* ln2_b  = (const float*)d_in[22];
    const float* lnf_g  = (const float*)d_in[23];
    const float* lnf_b  = (const float*)d_in[24];
    const float* proj_W = (const float*)d_in[25];
    const float* proj_b = (const float*)d_in[26];

    float *means, *stdev, *xn, *h, *coeffs, *q, *k, *v, *qn2, *kn2, *sc,
          *smaxb, *sinvb, *attn, *rec, *o, *x1, *y, *z, *hf, *dec;
    cudaGetSymbolAddress((void**)&means,  g_means);
    cudaGetSymbolAddress((void**)&stdev,  g_stdev);
    cudaGetSymbolAddress((void**)&xn,     g_xn);
    cudaGetSymbolAddress((void**)&h,      g_h);
    cudaGetSymbolAddress((void**)&coeffs, g_coeffs);
    cudaGetSymbolAddress((void**)&q,      g_q);
    cudaGetSymbolAddress((void**)&k,      g_k);
    cudaGetSymbolAddress((void**)&v,      g_v);
    cudaGetSymbolAddress((void**)&qn2,    g_qn2);
    cudaGetSymbolAddress((void**)&kn2,    g_kn2);
    cudaGetSymbolAddress((void**)&sc,     g_sc);
    cudaGetSymbolAddress((void**)&smaxb,  g_smax);
    cudaGetSymbolAddress((void**)&sinvb,  g_sinv);
    cudaGetSymbolAddress((void**)&attn,   g_attn);
    cudaGetSymbolAddress((void**)&rec,    g_rec);
    cudaGetSymbolAddress((void**)&o,      g_o);
    cudaGetSymbolAddress((void**)&x1,     g_x1);
    cudaGetSymbolAddress((void**)&y,      g_y);
    cudaGetSymbolAddress((void**)&z,      g_z);
    cudaGetSymbolAddress((void**)&hf,     g_hf);
    cudaGetSymbolAddress((void**)&dec,    g_dec);

    // Input stats + normalized transpose
    k_stats<<<dim3(BB, (NCH + 31) / 32), dim3(32, 8)>>>(x_enc, means, stdev);
    k_normT<<<dim3(SS / 32, (NCH + 31) / 32, BB), dim3(32, 8)>>>(x_enc, means, stdev, xn);

    // Embedding: h[bn, d] = xn[bn, :] . emb_W[d, :]
    k_mma<<<dim3(DD / 128, (BN + 127) / 128), 256>>>(xn, emb_W, emb_b, h, BN, DD, SS);

    const dim3 gQKV(DD / 128, (BN * 4 + 127) / 128, 3);
    const dim3 gD  (DD / 128, (BN + 127) / 128);

    for (int l = 0; l < 2; l++) {
        const float* h0l = h0 + (size_t)l * NCH * 3;
        const float* h1l = h1 + (size_t)l * NCH * 3;
        const float* g0l = g0 + (size_t)l * NCH * 3;
        const float* g1l = g1 + (size_t)l * NCH * 3;

        k_swt_dec<<<BN, DD>>>(h, h0l, h1l, coeffs);

        k_qkv<<<gQKV, 256>>>(coeffs,
                             Wq + (size_t)l * DD * DD, Wk + (size_t)l * DD * DD,
                             Wv + (size_t)l * DD * DD,
                             bq + l * DD, bk + l * DD, bv + l * DD, q, k, v);

        k_qknorms<<<dim3(2, BB * 4), 256>>>(q, k, qn2, kn2);
        k_dot_geom<<<dim3(4, 4, BB * 4), 256>>>(q, k, qn2, kn2, sc);
        k_rowstats<<<BB * 4 * DD / 8, 256>>>(sc, smaxb, sinvb);
        k_av<<<dim3(4, (NCH + 127) / 128, BB * 4), 256>>>(v, sc, smaxb, sinvb, attn);

        k_swt_rec<<<BN, DD>>>(attn, g0l, g1l, rec);

        k_mma<<<gD, 256>>>(rec, Wo + (size_t)l * DD * DD, bo + l * DD, o, BN, DD, DD);
        k_ln<<<BN, 256>>>(h, o, ln1_g + l * DD, ln1_b + l * DD, x1);

        k_mma_gelu<<<dim3(DFF / 128, (BN + 127) / 128), 256>>>(
            x1, W1 + (size_t)l * DFF * DD, b1 + l * DFF, y, BN, DFF, DD);
        k_mma<<<gD, 256>>>(y, W2 + (size_t)l * DD * DFF, b2 + l * DD, z, BN, DD, DFF);
        k_ln<<<BN, 256>>>(x1, z, ln2_g + l * DD, ln2_b + l * DD, h);
    }

    // Final LN + projection + de-normalization
    k_ln<<<BN, 256>>>(h, nullptr, lnf_g, lnf_b, hf);
    k_mma<<<dim3((PP + 127) / 128, (BN + 127) / 128), 256>>>(hf, proj_W, proj_b, dec, BN, PP, DD);
    k_dec_out<<<(BB * PP * NCH + 255) / 256, 256>>>(dec, means, stdev, (float*)d_out);

    // Tuple tail: (dec, means, stdev) flattened
    if (out_size >= BB * PP * NCH + 2 * BN)
        k_tail<<<(BN + 255) / 256, 256>>>(means, stdev, (float*)d_out + BB * PP * NCH);
}

// round 14
// speedup vs baseline: 1.0016x; 1.0016x over previous
#include <cuda_runtime.h>
#include <math.h>
#include <stdint.h>

// Problem constants
#define BB   16
#define SS   512
#define NCH  321
#define DD   512
#define DFF  2048
#define PP   96
#define BN   (BB*NCH)          // 5136 tokens

// ---------------------------------------------------------------------------
// Scratch buffers
// ---------------------------------------------------------------------------
__device__ float g_means[BN];
__device__ float g_stdev[BN];
__device__ float g_xn    [(size_t)BN*SS];
__device__ float g_h     [(size_t)BN*DD];
__device__ float g_coeffs[(size_t)BN*4*DD];
__device__ float g_q     [(size_t)BN*4*DD];
__device__ float g_k     [(size_t)BN*4*DD];
__device__ float g_v     [(size_t)BN*4*DD];
__device__ float g_qn2   [BB*4*DD];
__device__ float g_kn2   [BB*4*DD];
__device__ float g_sc    [(size_t)BB*4*DD*DD];   // 64 x 512 x 512
__device__ float g_smax  [BB*4*DD];
__device__ float g_sinv  [BB*4*DD];
__device__ float g_attn  [(size_t)BN*4*DD];
__device__ float g_rec   [(size_t)BN*DD];
__device__ float g_o     [(size_t)BN*DD];
__device__ float g_x1    [(size_t)BN*DD];
__device__ float g_y     [(size_t)BN*DFF];
__device__ float g_z     [(size_t)BN*DD];
__device__ float g_hf    [(size_t)BN*DD];
__device__ float g_dec   [(size_t)BN*PP];

// ---------------------------------------------------------------------------
// Helpers
// ---------------------------------------------------------------------------
__device__ __forceinline__ uint32_t f2tf(float x) {
    uint32_t r;
    asm("cvt.rna.tf32.f32 %0, %1;" : "=r"(r) : "f"(x));
    return r;
}

#define MMA8(cc, A0, A1, A2, A3, B0, B1)                                     \
    asm volatile("mma.sync.aligned.m16n8k8.row.col.f32.tf32.tf32.f32 "      \
        "{%0,%1,%2,%3}, {%4,%5,%6,%7}, {%8,%9}, {%0,%1,%2,%3};"             \
        : "+f"(cc[0]), "+f"(cc[1]), "+f"(cc[2]), "+f"(cc[3])                \
        : "r"(A0), "r"(A1), "r"(A2), "r"(A3), "r"(B0), "r"(B1))

__device__ __forceinline__ float blk_sum(float v, float* sh) {
    #pragma unroll
    for (int o = 16; o; o >>= 1) v += __shfl_xor_sync(0xffffffffu, v, o);
    int t = threadIdx.x;
    if ((t & 31) == 0) sh[t >> 5] = v;
    __syncthreads();
    v = sh[0] + sh[1] + sh[2] + sh[3] + sh[4] + sh[5] + sh[6] + sh[7];
    __syncthreads();
    return v;
}

// ---------------------------------------------------------------------------
// TF32 tensor-core GEMM tile: 128x128 CTA, BK=16, 8 warps (2x4), warp 64x32.
// Depth-2 register prefetch: while computing k-stage i, the global loads for
// stage i+2 are in flight and stage i+1 is staged from registers to smem.
// Smem k-permuted: col = (k&3)*4 + (k>>2), row pad 20 words -> LDS.128 frags.
// LAYOUT 0 (NT): C[m,n] = sum_k A[m*lda+k] * B[n*ldb+k]   (K % 16 == 0)
// LAYOUT 1 (TN): C[m,n] = sum_k A[k*lda+m] * B[k*ldb+n]   (arbitrary K)
// EPI 0: +bias    EPI 1: +bias, exact GELU    EPI 2: geometric wedge score
// SOFTB: B rows are attention scores; apply exp(x - smax[row]) * sinv[row]
// ---------------------------------------------------------------------------
template<int LAYOUT, int EPI, bool SOFTB = false>
__device__ __forceinline__ void mma_tile(
    const float* __restrict__ A, const float* __restrict__ Bm,
    const float* __restrict__ bias, float* __restrict__ C,
    int M, int N, int K, int lda, int ldb, int ldc,
    const float* __restrict__ rown, const float* __restrict__ coln,
    const float* __restrict__ smax = nullptr, const float* __restrict__ sinv = nullptr)
{
    constexpr int BKP = 20;
    __shared__ uint32_t As[2][128 * BKP];
    __shared__ uint32_t Bs[2][128 * BKP];

    const int tid  = threadIdx.x;
    const int lane = tid & 31;
    const int g    = lane >> 2;
    const int t    = lane & 3;
    const int wid  = tid >> 5;
    const int wm   = (wid >> 2) * 64;
    const int wn   = (wid & 3) * 32;
    const int m0   = blockIdx.y * 128;
    const int n0   = blockIdx.x * 128;

    float c[4][4][4];
    #pragma unroll
    for (int i = 0; i < 4; i++)
        #pragma unroll
        for (int j = 0; j < 4; j++)
            #pragma unroll
            for (int r = 0; r < 4; r++) c[i][j][r] = 0.f;

    // loader indices
    const int r_nt  = tid >> 1;          // 0..127
    const int kg_nt = (tid & 1) * 8;     // 0 or 8
    const int kr_tn = tid >> 4;          // 0..15
    const int mc_tn = (tid & 15) * 8;    // 0..120
    const bool aok = (m0 + ((LAYOUT == 0) ? r_nt : mc_tn)) < M;
    const bool bok = (n0 + ((LAYOUT == 0) ? r_nt : mc_tn)) < N;

    float mxv = 0.f, invv = 1.f;
    if (SOFTB) {
        const int rr = n0 + r_nt;
        if (rr < N) { mxv = smax[rr]; invv = sinv[rr]; }
    }
    #define XB(x) (SOFTB ? expf((x) - mxv) * invv : (x))

    float va0[8], vb0[8], va1[8], vb1[8];

    #define FETCH(k0, VA, VB)                                                 \
        {                                                                     \
            _Pragma("unroll")                                                 \
            for (int j = 0; j < 8; j++) { VA[j] = 0.f; VB[j] = 0.f; }         \
            if (LAYOUT == 0) {                                                \
                if (aok) {                                                    \
                    const float4* p = (const float4*)(A + (size_t)(m0 + r_nt) * lda + (k0) + kg_nt); \
                    float4 x0 = p[0], x1 = p[1];                              \
                    VA[0]=x0.x; VA[1]=x0.y; VA[2]=x0.z; VA[3]=x0.w;           \
                    VA[4]=x1.x; VA[5]=x1.y; VA[6]=x1.z; VA[7]=x1.w;           \
                }                                                             \
                if (bok) {                                                    \
                    const float4* p = (const float4*)(Bm + (size_t)(n0 + r_nt) * ldb + (k0) + kg_nt); \
                    float4 x0 = p[0], x1 = p[1];                              \
                    VB[0]=x0.x; VB[1]=x0.y; VB[2]=x0.z; VB[3]=x0.w;           \
                    VB[4]=x1.x; VB[5]=x1.y; VB[6]=x1.z; VB[7]=x1.w;           \
                }                                                             \
            } else {                                                          \
                const int gk = (k0) + kr_tn;                                  \
                if (gk < K) {                                                 \
                    if (aok) {                                                \
                        const float4* pa = (const float4*)(A + (size_t)gk * lda + m0 + mc_tn); \
                        float4 x0 = pa[0], x1 = pa[1];                        \
                        VA[0]=x0.x; VA[1]=x0.y; VA[2]=x0.z; VA[3]=x0.w;       \
                        VA[4]=x1.x; VA[5]=x1.y; VA[6]=x1.z; VA[7]=x1.w;       \
                    }                                                         \
                    if (bok) {                                                \
                        const float4* pb = (const float4*)(Bm + (size_t)gk * ldb + n0 + mc_tn); \
                        float4 y0 = pb[0], y1 = pb[1];                        \
                        VB[0]=y0.x; VB[1]=y0.y; VB[2]=y0.z; VB[3]=y0.w;       \
                        VB[4]=y1.x; VB[5]=y1.y; VB[6]=y1.z; VB[7]=y1.w;       \
                    }                                                         \
                }                                                             \
            }                                                                 \
        }

    #define STAGE(VA, VB, bf)                                                \
        {                                                                     \
            if (LAYOUT == 0) {                                                \
                const int cb = kg_nt >> 2;      /* 0 or 2 */                  \
                _Pragma("unroll")                                             \
                for (int j = 0; j < 4; j++) {                                 \
                    uint2 pa = make_uint2(f2tf(VA[j]), f2tf(VA[j+4]));        \
                    *(uint2*)&As[bf][r_nt * BKP + 4*j + cb] = pa;             \
                    uint2 pb = make_uint2(f2tf(XB(VB[j])), f2tf(XB(VB[j+4])));\
                    *(uint2*)&Bs[bf][r_nt * BKP + 4*j + cb] = pb;             \
                }                                                             \
            } else {                                                          \
                const int p = (kr_tn & 3) * 4 + (kr_tn >> 2);                 \
                _Pragma("unroll")                                             \
                for (int j = 0; j < 8; j++) {                                 \
                    As[bf][(mc_tn + j) * BKP + p] = f2tf(VA[j]);              \
                    Bs[bf][(mc_tn + j) * BKP + p] = f2tf(VB[j]);              \
                }                                                             \
            }                                                                 \
        }

    #define COMPUTE(bf)                                                      \
        {                                                                     \
            uint32_t bfr[4][4];                                               \
            _Pragma("unroll")                                                 \
            for (int j = 0; j < 4; j++)                                       \
                *(uint4*)bfr[j] = *(const uint4*)&Bs[bf][(wn + j * 8 + g) * BKP + 4 * t]; \
            _Pragma("unroll")                                                 \
            for (int i = 0; i < 4; i++) {                                     \
                uint32_t a0[4], a1[4];                                        \
                *(uint4*)a0 = *(const uint4*)&As[bf][(wm + i * 16 + g)     * BKP + 4 * t]; \
                *(uint4*)a1 = *(const uint4*)&As[bf][(wm + i * 16 + 8 + g) * BKP + 4 * t]; \
                _Pragma("unroll")                                             \
                for (int j = 0; j < 4; j++) {                                 \
                    MMA8(c[i][j], a0[0], a1[0], a0[1], a1[1], bfr[j][0], bfr[j][1]); \
                    MMA8(c[i][j], a0[2], a1[2], a0[3], a1[3], bfr[j][2], bfr[j][3]); \
                }                                                             \
            }                                                                 \
        }

    const int Kt = (LAYOUT == 0) ? K : ((K + 15) & ~15);
    const int S  = Kt >> 4;            // total k16 stages (>= 2 at all sites)
    const int T  = S - 2;              // main-loop iterations

    FETCH(0, va0, vb0);
    STAGE(va0, vb0, 0);
    FETCH(16, va1, vb1);
    __syncthreads();

    int buf = 0;
    int k2  = 32;
    for (int it = 0; it + 2 <= T; it += 2) {
        FETCH(k2, va0, vb0); k2 += 16;
        COMPUTE(buf);
        STAGE(va1, vb1, buf ^ 1);
        __syncthreads();
        buf ^= 1;
        FETCH(k2, va1, vb1); k2 += 16;
        COMPUTE(buf);
        STAGE(va0, vb0, buf ^ 1);
        __syncthreads();
        buf ^= 1;
    }
    if (T & 1) {
        FETCH(k2, va0, vb0);
        COMPUTE(buf);
        STAGE(va1, vb1, buf ^ 1);
        __syncthreads();
        buf ^= 1;
        COMPUTE(buf);
        STAGE(va0, vb0, buf ^ 1);
        __syncthreads();
        buf ^= 1;
        COMPUTE(buf);
    } else {
        COMPUTE(buf);
        STAGE(va1, vb1, buf ^ 1);
        __syncthreads();
        buf ^= 1;
        COMPUTE(buf);
    }

    #undef FETCH
    #undef STAGE
    #undef COMPUTE
    #undef XB

    // Epilogue
    const float scale = rsqrtf(321.0f);
    #pragma unroll
    for (int i = 0; i < 4; i++) {
        #pragma unroll
        for (int h = 0; h < 2; h++) {
            const int gm = m0 + wm + i * 16 + g + h * 8;
            if (gm >= M) continue;
            const float rn = (EPI == 2) ? rown[gm] : 0.f;
            #pragma unroll
            for (int j = 0; j < 4; j++) {
                const int gn = n0 + wn + j * 8 + 2 * t;
                float v0 = c[i][j][h * 2 + 0];
                float v1 = c[i][j][h * 2 + 1];
                if (EPI <= 1 && bias) {
                    if (gn     < N) v0 += bias[gn];
                    if (gn + 1 < N) v1 += bias[gn + 1];
                }
                if (EPI == 1) {
                    v0 = 0.5f * v0 * (1.f + erff(v0 * 0.70710678118654752f));
                    v1 = 0.5f * v1 * (1.f + erff(v1 * 0.70710678118654752f));
                }
                if (EPI == 2) {
                    float cn0 = (gn     < N) ? coln[gn]     : 0.f;
                    float cn1 = (gn + 1 < N) ? coln[gn + 1] : 0.f;
                    float w0 = sqrtf(fmaxf(rn * cn0 - v0 * v0, 0.f) + 1e-8f);
                    float w1 = sqrtf(fmaxf(rn * cn1 - v1 * v1, 0.f) + 1e-8f);
                    v0 = (0.7f * v0 + 0.3f * w0) * scale;
                    v1 = (0.7f * v1 + 0.3f * w1) * scale;
                }
                float* p = C + (size_t)gm * ldc + gn;
                if (gn + 1 < N)      *(float2*)p = make_float2(v0, v1);
                else if (gn < N)     *p = v0;
            }
        }
    }
}

__global__ void __launch_bounds__(256, 2) k_mma(
    const float* __restrict__ A, const float* __restrict__ B,
    const float* __restrict__ bias, float* __restrict__ C, int M, int N, int K)
{
    mma_tile<0, 0>(A, B, bias, C, M, N, K, K, K, N, nullptr, nullptr);
}
__global__ void __launch_bounds__(256, 2) k_mma_gelu(
    const float* __restrict__ A, const float* __restrict__ B,
    const float* __restrict__ bias, float* __restrict__ C, int M, int N, int K)
{
    mma_tile<0, 1>(A, B, bias, C, M, N, K, K, K, N, nullptr, nullptr);
}

// Fused Q/K/V projection (blockIdx.z selects the projection)
__global__ void __launch_bounds__(256, 2) k_qkv(
    const float* __restrict__ coeffs,
    const float* __restrict__ Wq, const float* __restrict__ Wk, const float* __restrict__ Wv,
    const float* __restrict__ bq, const float* __restrict__ bk, const float* __restrict__ bv,
    float* __restrict__ q, float* __restrict__ k, float* __restrict__ v)
{
    const float* W; const float* bi; float* out;
    if (blockIdx.z == 0)      { W = Wq; bi = bq; out = q; }
    else if (blockIdx.z == 1) { W = Wk; bi = bk; out = k; }
    else                      { W = Wv; bi = bv; out = v; }
    mma_tile<0, 0>(coeffs, W, bi, out, BN * 4, DD, DD, DD, DD, DD, nullptr, nullptr);
}

// dot + geometric score, batched over z = b*4 + head (TN over channels)
__global__ void __launch_bounds__(256, 2) k_dot_geom(
    const float* __restrict__ q, const float* __restrict__ k,
    const float* __restrict__ qn2, const float* __restrict__ kn2,
    float* __restrict__ sc)
{
    const int z = blockIdx.z;
    const int b = z >> 2, m = z & 3;
    const float* A  = q + (size_t)b * NCH * 2048 + m * 512;
    const float* Bm = k + (size_t)b * NCH * 2048 + m * 512;
    float* C = sc + (size_t)z * DD * DD;
    mma_tile<1, 2>(A, Bm, nullptr, C, DD, DD, NCH, 2048, 2048, DD,
                   qn2 + z * DD, kn2 + z * DD);
}

// attn out: C[d, l] = sum_s V[d,s] * P[l,s]; softmax applied on the fly to P
__global__ void __launch_bounds__(256, 2) k_av(
    const float* __restrict__ v, const float* __restrict__ pr,
    const float* __restrict__ smax, const float* __restrict__ sinv,
    float* __restrict__ attn)
{
    const int z = blockIdx.z;
    const int b = z >> 2, m = z & 3;
    const float* A  = v  + (size_t)b * NCH * 2048 + m * 512;
    const float* Bm = pr + (size_t)z * DD * DD;
    float* C = attn + (size_t)b * NCH * 2048 + m * 512;
    mma_tile<0, 0, true>(A, Bm, nullptr, C, NCH, DD, DD, 2048, DD, 2048,
                         nullptr, nullptr, smax + (size_t)z * DD, sinv + (size_t)z * DD);
}

// Per-row max and 1/sum(exp) over 512 score columns (one warp per row)
__global__ void __launch_bounds__(256) k_rowstats(
    const float* __restrict__ sc, float* __restrict__ smax, float* __restrict__ sinv)
{
    const int row  = blockIdx.x * 8 + (threadIdx.x >> 5);
    const int lane = threadIdx.x & 31;
    const float* p = sc + (size_t)row * DD;
    float v[16];
    float mx = -1e30f;
    #pragma unroll
    for (int i = 0; i < 16; i++) { v[i] = p[lane + 32 * i]; mx = fmaxf(mx, v[i]); }
    #pragma unroll
    for (int o = 16; o; o >>= 1) mx = fmaxf(mx, __shfl_xor_sync(0xffffffffu, mx, o));
    float s = 0.f;
    #pragma unroll
    for (int i = 0; i < 16; i++) s += expf(v[i] - mx);
    #pragma unroll
    for (int o = 16; o; o >>= 1) s += __shfl_xor_sync(0xffffffffu, s, o);
    if (lane == 0) { smax[row] = mx; sinv[row] = 1.f / s; }
}

// ---------------------------------------------------------------------------
// Input stats: means/stdev over S per (b, n)
// ---------------------------------------------------------------------------
__global__ void k_stats(const float* __restrict__ x,
                        float* __restrict__ means, float* __restrict__ stdev)
{
    const int b = blockIdx.x;
    const int n = blockIdx.y * 32 + threadIdx.x;
    float s = 0.f, s2 = 0.f;
    if (n < NCH) {
        for (int t = threadIdx.y; t < SS; t += 8) {
            float vv = x[((size_t)b * SS + t) * NCH + n];
            s += vv; s2 = fmaf(vv, vv, s2);
        }
    }
    __shared__ float sh[8][32], sh2[8][32];
    sh [threadIdx.y][threadIdx.x] = s;
    sh2[threadIdx.y][threadIdx.x] = s2;
    __syncthreads();
    if (threadIdx.y == 0 && n < NCH) {
        float a = 0.f, a2 = 0.f;
        #pragma unroll
        for (int i = 0; i < 8; i++) { a += sh[i][threadIdx.x]; a2 += sh2[i][threadIdx.x]; }
        float mu  = a * (1.f / SS);
        float var = a2 * (1.f / SS) - mu * mu;
        means[b * NCH + n] = mu;
        stdev[b * NCH + n] = sqrtf(var + 1e-5f);
    }
}

// Normalize + transpose: xn[b, n, s] = (x[b, s, n] - mu) / sd
__global__ void k_normT(const float* __restrict__ x,
                        const float* __restrict__ means, const float* __restrict__ stdev,
                        float* __restrict__ xn)
{
    __shared__ float tile[32][33];
    const int b  = blockIdx.z;
    const int s0 = blockIdx.x * 32;
    const int n0 = blockIdx.y * 32;
    #pragma unroll
    for (int r = 0; r < 4; r++) {
        int ss = s0 + threadIdx.y + r * 8;
        int nn = n0 + threadIdx.x;
        tile[threadIdx.y + r * 8][threadIdx.x] =
            (nn < NCH) ? x[((size_t)b * SS + ss) * NCH + nn] : 0.f;
    }
    __syncthreads();
    #pragma unroll
    for (int r = 0; r < 4; r++) {
        int nn = n0 + threadIdx.y + r * 8;
        int ss = s0 + threadIdx.x;
        if (nn < NCH) {
            float mu = means[b * NCH + nn];
            float sd = stdev[b * NCH + nn];
            xn[((size_t)b * NCH + nn) * SS + ss] =
                (tile[threadIdx.x][threadIdx.y + r * 8] - mu) / sd;
        }
    }
}

// ---------------------------------------------------------------------------
// SWT decomposition / reconstruction
// ---------------------------------------------------------------------------
__global__ void __launch_bounds__(512) k_swt_dec(
    const float* __restrict__ h, const float* __restrict__ h0,
    const float* __restrict__ h1, float* __restrict__ coeffs)
{
    const int bn = blockIdx.x;
    const int n  = bn % NCH;
    const int d  = threadIdx.x;
    __shared__ float buf[2][DD];
    buf[0][d] = h[(size_t)bn * DD + d];
    float f0[3], f1[3];
    #pragma unroll
    for (int kk = 0; kk < 3; kk++) { f0[kk] = h0[n * 3 + kk]; f1[kk] = h1[n * 3 + kk]; }
    __syncthreads();
    int cur = 0, dil = 1;
    const int pl[3] = {1, 1, 2};
    #pragma unroll
    for (int m = 0; m < 3; m++) {
        float det = 0.f, app = 0.f;
        #pragma unroll
        for (int kk = 0; kk < 3; kk++) {
            int idx = (d + kk * dil - pl[m] + DD) & (DD - 1);
            float vv = buf[cur][idx];
            det = fmaf(f1[kk], vv, det);
            app = fmaf(f0[kk], vv, app);
        }
        coeffs[((size_t)bn * 4 + (3 - m)) * DD + d] = det;
        buf[cur ^ 1][d] = app;
        __syncthreads();
        cur ^= 1; dil <<= 1;
    }
    coeffs[(size_t)bn * 4 * DD + d] = buf[cur][d];
}

__global__ void __launch_bounds__(512) k_swt_rec(
    const float* __restrict__ c, const float* __restrict__ g0,
    const float* __restrict__ g1, float* __restrict__ rec)
{
    const int bn = blockIdx.x;
    const int n  = bn % NCH;
    const int d  = threadIdx.x;
    __shared__ float app[2][DD];
    __shared__ float det[DD];
    app[0][d] = c[(size_t)bn * 4 * DD + d];
    float f0[3], f1[3];
    #pragma unroll
    for (int kk = 0; kk < 3; kk++) { f0[kk] = g0[n * 3 + kk]; f1[kk] = g1[n * 3 + kk]; }
    int cur = 0, dil = 4;
    const int pl[3] = {6, 3, 1};
    #pragma unroll
    for (int i = 0; i < 3; i++) {
        det[d] = c[((size_t)bn * 4 + 1 + i) * DD + d];
        __syncthreads();
        float acc = 0.f;
        #pragma unroll
        for (int kk = 0; kk < 3; kk++) {
            int idx = (d + kk * dil - pl[i] + DD) & (DD - 1);
            acc = fmaf(f0[kk], app[cur][idx], acc);
            acc = fmaf(f1[kk], det[idx], acc);
        }
        app[cur ^ 1][d] = 0.5f * acc;
        __syncthreads();
        cur ^= 1; dil >>= 1;
    }
    rec[(size_t)bn * DD + d] = app[cur][d];
}

// Row norms of Q and K over channels, per (b, head, l)
__global__ void __launch_bounds__(256) k_qknorms(
    const float* __restrict__ q, const float* __restrict__ k,
    float* __restrict__ qn2, float* __restrict__ kn2)
{
    const int z = blockIdx.y;
    const int b = z >> 2, m = z & 3;
    const int l = blockIdx.x * 256 + threadIdx.x;
    const size_t base = (size_t)b * NCH * 2048 + m * 512 + l;
    float sq = 0.f, sk = 0.f;
    for (int j = 0; j < NCH; j++) {
        float a = q[base + (size_t)j * 2048]; sq = fmaf(a, a, sq);
        float c = k[base + (size_t)j * 2048]; sk = fmaf(c, c, sk);
    }
    qn2[z * DD + l] = sq;
    kn2[z * DD + l] = sk;
}

// LayerNorm over D=512 (optionally fused residual add)
__global__ void __launch_bounds__(256) k_ln(
    const float* __restrict__ x, const float* __restrict__ res,
    const float* __restrict__ g, const float* __restrict__ bt,
    float* __restrict__ out)
{
    const size_t base = (size_t)blockIdx.x * DD;
    const int t = threadIdx.x;
    __shared__ float sh[8];
    float v0 = x[base + t], v1 = x[base + t + 256];
    if (res) { v0 += res[base + t]; v1 += res[base + t + 256]; }
    float s = blk_sum(v0 + v1, sh);
    float mu = s * (1.f / DD);
    float d0 = v0 - mu, d1 = v1 - mu;
    float vs = blk_sum(d0 * d0 + d1 * d1, sh);
    float rs = rsqrtf(vs * (1.f / DD) + 1e-5f);
    out[base + t]       = d0 * rs * g[t]       + bt[t];
    out[base + t + 256] = d1 * rs * g[t + 256] + bt[t + 256];
}

// dec output: out[b, p, n] = dec[b, n, p] * stdev[b, n] + means[b, n]
__global__ void k_dec_out(const float* __restrict__ dec,
                          const float* __restrict__ means, const float* __restrict__ stdev,
                          float* __restrict__ out)
{
    const int idx = blockIdx.x * 256 + threadIdx.x;
    if (idx >= BB * PP * NCH) return;
    const int n = idx % NCH;
    const int p = (idx / NCH) % PP;
    const int b = idx / (NCH * PP);
    out[idx] = dec[((size_t)b * NCH + n) * PP + p] * stdev[b * NCH + n] + means[b * NCH + n];
}

__global__ void k_tail(const float* __restrict__ means, const float* __restrict__ stdev,
                       float* __restrict__ out)
{
    const int i = blockIdx.x * 256 + threadIdx.x;
    if (i < BN) { out[i] = means[i]; out[BN + i] = stdev[i]; }
}

// ---------------------------------------------------------------------------
// Launch
// ---------------------------------------------------------------------------
extern "C" void kernel_launch(void* const* d_in, const int* in_sizes, int n_in,
                              void* d_out, int out_size)
{
    const float* x_enc  = (const float*)d_in[0];
    const float* emb_W  = (const float*)d_in[1];
    const float* emb_b  = (const float*)d_in[2];
    const float* h0     = (const float*)d_in[3];
    const float* h1     = (const float*)d_in[4];
    const float* g0     = (const float*)d_in[5];
    const float* g1     = (const float*)d_in[6];
    const float* Wq     = (const float*)d_in[7];
    const float* bq     = (const float*)d_in[8];
    const float* Wk     = (const float*)d_in[9];
    const float* bk     = (const float*)d_in[10];
    const float* Wv     = (const float*)d_in[11];
    const float* bv     = (const float*)d_in[12];
    const float* Wo     = (const float*)d_in[13];
    const float* bo     = (const float*)d_in[14];
    const float* W1     = (const float*)d_in[15];
    const float* b1     = (const float*)d_in[16];
    const float* W2     = (const float*)d_in[17];
    const float* b2     = (const float*)d_in[18];
    const float* ln1_g  = (const float*)d_in[19];
    const float* ln1_b  = (const float*)d_in[20];
    const float* ln2_g  = (const float*)d_in[21];
    const float* ln2_b  = (const float*)d_in[22];
    const float* lnf_g  = (const float*)d_in[23];
    const float* lnf_b  = (const float*)d_in[24];
    const float* proj_W = (const float*)d_in[25];
    const float* proj_b = (const float*)d_in[26];

    float *means, *stdev, *xn, *h, *coeffs, *q, *k, *v, *qn2, *kn2, *sc,
          *smaxb, *sinvb, *attn, *rec, *o, *x1, *y, *z, *hf, *dec;
    cudaGetSymbolAddress((void**)&means,  g_means);
    cudaGetSymbolAddress((void**)&stdev,  g_stdev);
    cudaGetSymbolAddress((void**)&xn,     g_xn);
    cudaGetSymbolAddress((void**)&h,      g_h);
    cudaGetSymbolAddress((void**)&coeffs, g_coeffs);
    cudaGetSymbolAddress((void**)&q,      g_q);
    cudaGetSymbolAddress((void**)&k,      g_k);
    cudaGetSymbolAddress((void**)&v,      g_v);
    cudaGetSymbolAddress((void**)&qn2,    g_qn2);
    cudaGetSymbolAddress((void**)&kn2,    g_kn2);
    cudaGetSymbolAddress((void**)&sc,     g_sc);
    cudaGetSymbolAddress((void**)&smaxb,  g_smax);
    cudaGetSymbolAddress((void**)&sinvb,  g_sinv);
    cudaGetSymbolAddress((void**)&attn,   g_attn);
    cudaGetSymbolAddress((void**)&rec,    g_rec);
    cudaGetSymbolAddress((void**)&o,      g_o);
    cudaGetSymbolAddress((void**)&x1,     g_x1);
    cudaGetSymbolAddress((void**)&y,      g_y);
    cudaGetSymbolAddress((void**)&z,      g_z);
    cudaGetSymbolAddress((void**)&hf,     g_hf);
    cudaGetSymbolAddress((void**)&dec,    g_dec);

    // Input stats + normalized transpose
    k_stats<<<dim3(BB, (NCH + 31) / 32), dim3(32, 8)>>>(x_enc, means, stdev);
    k_normT<<<dim3(SS / 32, (NCH + 31) / 32, BB), dim3(32, 8)>>>(x_enc, means, stdev, xn);

    // Embedding: h[bn, d] = xn[bn, :] . emb_W[d, :]
    k_mma<<<dim3(DD / 128, (BN + 127) / 128), 256>>>(xn, emb_W, emb_b, h, BN, DD, SS);

    const dim3 gQKV(DD / 128, (BN * 4 + 127) / 128, 3);
    const dim3 gD  (DD / 128, (BN + 127) / 128);

    for (int l = 0; l < 2; l++) {
        const float* h0l = h0 + (size_t)l * NCH * 3;
        const float* h1l = h1 + (size_t)l * NCH * 3;
        const float* g0l = g0 + (size_t)l * NCH * 3;
        const float* g1l = g1 + (size_t)l * NCH * 3;

        k_swt_dec<<<BN, DD>>>(h, h0l, h1l, coeffs);

        k_qkv<<<gQKV, 256>>>(coeffs,
                             Wq + (size_t)l * DD * DD, Wk + (size_t)l * DD * DD,
                             Wv + (size_t)l * DD * DD,
                             bq + l * DD, bk + l * DD, bv + l * DD, q, k, v);

        k_qknorms<<<dim3(2, BB * 4), 256>>>(q, k, qn2, kn2);
        k_dot_geom<<<dim3(4, 4, BB * 4), 256>>>(q, k, qn2, kn2, sc);
        k_rowstats<<<BB * 4 * DD / 8, 256>>>(sc, smaxb, sinvb);
        k_av<<<dim3(4, (NCH + 127) / 128, BB * 4), 256>>>(v, sc, smaxb, sinvb, attn);

        k_swt_rec<<<BN, DD>>>(attn, g0l, g1l, rec);

        k_mma<<<gD, 256>>>(rec, Wo + (size_t)l * DD * DD, bo + l * DD, o, BN, DD, DD);
        k_ln<<<BN, 256>>>(h, o, ln1_g + l * DD, ln1_b + l * DD, x1);

        k_mma_gelu<<<dim3(DFF / 128, (BN + 127) / 128), 256>>>(
            x1, W1 + (size_t)l * DFF * DD, b1 + l * DFF, y, BN, DFF, DD);
        k_mma<<<gD, 256>>>(y, W2 + (size_t)l * DD * DFF, b2 + l * DD, z, BN, DD, DFF);
        k_ln<<<BN, 256>>>(x1, z, ln2_g + l * DD, ln2_b + l * DD, h);
    }

    // Final LN + projection + de-normalization
    k_ln<<<BN, 256>>>(h, nullptr, lnf_g, lnf_b, hf);
    k_mma<<<dim3((PP + 127) / 128, (BN + 127) / 128), 256>>>(hf, proj_W, proj_b, dec, BN, PP, DD);
    k_dec_out<<<(BB * PP * NCH + 255) / 256, 256>>>(dec, means, stdev, (float*)d_out);

    // Tuple tail: (dec, means, stdev) flattened
    if (out_size >= BB * PP * NCH + 2 * BN)
        k_tail<<<(BN + 255) / 256, 256>>>(means, stdev, (float*)d_out + BB * PP * NCH);
}

// round 15
// speedup vs baseline: 1.2722x; 1.2701x over previous
#include <cuda_runtime.h>
#include <math.h>
#include <stdint.h>

// Problem constants
#define BB   16
#define SS   512
#define NCH  321
#define DD   512
#define DFF  2048
#define PP   96
#define BN   (BB*NCH)          // 5136 tokens

// ---------------------------------------------------------------------------
// Scratch buffers
// ---------------------------------------------------------------------------
__device__ float g_means[BN];
__device__ float g_stdev[BN];
__device__ float g_xn    [(size_t)BN*SS];
__device__ float g_h     [(size_t)BN*DD];
__device__ float g_coeffs[(size_t)BN*4*DD];
__device__ float g_q     [(size_t)BN*4*DD];
__device__ float g_k     [(size_t)BN*4*DD];
__device__ float g_v     [(size_t)BN*4*DD];
__device__ float g_qn2   [BB*4*DD];
__device__ float g_kn2   [BB*4*DD];
__device__ float g_sc    [(size_t)BB*4*DD*DD];   // 64 x 512 x 512
__device__ float g_smax  [BB*4*DD];
__device__ float g_sinv  [BB*4*DD];
__device__ float g_attn  [(size_t)BN*4*DD];
__device__ float g_rec   [(size_t)BN*DD];
__device__ float g_o     [(size_t)BN*DD];
__device__ float g_x1    [(size_t)BN*DD];
__device__ float g_y     [(size_t)BN*DFF];
__device__ float g_z     [(size_t)BN*DD];
__device__ float g_hf    [(size_t)BN*DD];
__device__ float g_dec   [(size_t)BN*PP];

// ---------------------------------------------------------------------------
// Helpers
// ---------------------------------------------------------------------------
__device__ __forceinline__ uint32_t f2tf(float x) {
    uint32_t r;
    asm("cvt.rna.tf32.f32 %0, %1;" : "=r"(r) : "f"(x));
    return r;
}

#define MMA8(cc, A0, A1, A2, A3, B0, B1)                                     \
    asm volatile("mma.sync.aligned.m16n8k8.row.col.f32.tf32.tf32.f32 "      \
        "{%0,%1,%2,%3}, {%4,%5,%6,%7}, {%8,%9}, {%0,%1,%2,%3};"             \
        : "+f"(cc[0]), "+f"(cc[1]), "+f"(cc[2]), "+f"(cc[3])                \
        : "r"(A0), "r"(A1), "r"(A2), "r"(A3), "r"(B0), "r"(B1))

__device__ __forceinline__ float blk_sum(float v, float* sh) {
    #pragma unroll
    for (int o = 16; o; o >>= 1) v += __shfl_xor_sync(0xffffffffu, v, o);
    int t = threadIdx.x;
    if ((t & 31) == 0) sh[t >> 5] = v;
    __syncthreads();
    v = sh[0] + sh[1] + sh[2] + sh[3] + sh[4] + sh[5] + sh[6] + sh[7];
    __syncthreads();
    return v;
}

// ---------------------------------------------------------------------------
// TF32 tensor-core GEMM tile: 128x128 CTA, BK=16, 8 warps (2x4), warp 64x32.
// Single register prefetch (fetch k+1 while computing k), double smem buffer,
// k-permuted smem: col = (k&3)*4 + (k>>2), row pad 20 words -> LDS.128 frags.
// Register budget tuned to fit 2 CTAs/SM under __launch_bounds__(256,2).
// LAYOUT 0 (NT): C[m,n] = sum_k A[m*lda+k] * B[n*ldb+k]   (K % 16 == 0)
// LAYOUT 1 (TN): C[m,n] = sum_k A[k*lda+m] * B[k*ldb+n]   (arbitrary K)
// EPI 0: +bias    EPI 1: +bias, exact GELU    EPI 2: geometric wedge score
// SOFTB: B rows are attention scores; apply exp(x - smax[row]) * sinv[row]
// ---------------------------------------------------------------------------
template<int LAYOUT, int EPI, bool SOFTB = false>
__device__ __forceinline__ void mma_tile(
    const float* __restrict__ A, const float* __restrict__ Bm,
    const float* __restrict__ bias, float* __restrict__ C,
    int M, int N, int K, int lda, int ldb, int ldc,
    const float* __restrict__ rown, const float* __restrict__ coln,
    const float* __restrict__ smax = nullptr, const float* __restrict__ sinv = nullptr)
{
    constexpr int BKP = 20;
    __shared__ uint32_t As[2][128 * BKP];
    __shared__ uint32_t Bs[2][128 * BKP];

    const int tid  = threadIdx.x;
    const int lane = tid & 31;
    const int g    = lane >> 2;
    const int t    = lane & 3;
    const int wid  = tid >> 5;
    const int wm   = (wid >> 2) * 64;
    const int wn   = (wid & 3) * 32;
    const int m0   = blockIdx.y * 128;
    const int n0   = blockIdx.x * 128;

    float c[4][4][4];
    #pragma unroll
    for (int i = 0; i < 4; i++)
        #pragma unroll
        for (int j = 0; j < 4; j++)
            #pragma unroll
            for (int r = 0; r < 4; r++) c[i][j][r] = 0.f;

    // loader indices
    const int r_nt  = tid >> 1;          // 0..127
    const int kg_nt = (tid & 1) * 8;     // 0 or 8
    const int kr_tn = tid >> 4;          // 0..15
    const int mc_tn = (tid & 15) * 8;    // 0..120
    const bool aok = (m0 + ((LAYOUT == 0) ? r_nt : mc_tn)) < M;
    const bool bok = (n0 + ((LAYOUT == 0) ? r_nt : mc_tn)) < N;

    float mxv = 0.f, invv = 1.f;
    if (SOFTB) {
        const int rr = n0 + r_nt;
        if (rr < N) { mxv = smax[rr]; invv = sinv[rr]; }
    }
    #define XB(x) (SOFTB ? expf((x) - mxv) * invv : (x))

    float va[8], vb[8];

    #define FETCH(k0)                                                         \
        {                                                                     \
            _Pragma("unroll")                                                 \
            for (int j = 0; j < 8; j++) { va[j] = 0.f; vb[j] = 0.f; }         \
            if (LAYOUT == 0) {                                                \
                if (aok) {                                                    \
                    const float4* p = (const float4*)(A + (size_t)(m0 + r_nt) * lda + (k0) + kg_nt); \
                    float4 x0 = p[0], x1 = p[1];                              \
                    va[0]=x0.x; va[1]=x0.y; va[2]=x0.z; va[3]=x0.w;           \
                    va[4]=x1.x; va[5]=x1.y; va[6]=x1.z; va[7]=x1.w;           \
                }                                                             \
                if (bok) {                                                    \
                    const float4* p = (const float4*)(Bm + (size_t)(n0 + r_nt) * ldb + (k0) + kg_nt); \
                    float4 x0 = p[0], x1 = p[1];                              \
                    vb[0]=x0.x; vb[1]=x0.y; vb[2]=x0.z; vb[3]=x0.w;           \
                    vb[4]=x1.x; vb[5]=x1.y; vb[6]=x1.z; vb[7]=x1.w;           \
                }                                                             \
            } else {                                                          \
                const int gk = (k0) + kr_tn;                                  \
                if (gk < K) {                                                 \
                    if (aok) {                                                \
                        const float4* pa = (const float4*)(A + (size_t)gk * lda + m0 + mc_tn); \
                        float4 x0 = pa[0], x1 = pa[1];                        \
                        va[0]=x0.x; va[1]=x0.y; va[2]=x0.z; va[3]=x0.w;       \
                        va[4]=x1.x; va[5]=x1.y; va[6]=x1.z; va[7]=x1.w;       \
                    }                                                         \
                    if (bok) {                                                \
                        const float4* pb = (const float4*)(Bm + (size_t)gk * ldb + n0 + mc_tn); \
                        float4 y0 = pb[0], y1 = pb[1];                        \
                        vb[0]=y0.x; vb[1]=y0.y; vb[2]=y0.z; vb[3]=y0.w;       \
                        vb[4]=y1.x; vb[5]=y1.y; vb[6]=y1.z; vb[7]=y1.w;       \
                    }                                                         \
                }                                                             \
            }                                                                 \
        }

    #define STAGE(bf)                                                        \
        {                                                                     \
            if (LAYOUT == 0) {                                                \
                const int cb = kg_nt >> 2;      /* 0 or 2 */                  \
                _Pragma("unroll")                                             \
                for (int j = 0; j < 4; j++) {                                 \
                    uint2 pa = make_uint2(f2tf(va[j]), f2tf(va[j+4]));        \
                    *(uint2*)&As[bf][r_nt * BKP + 4*j + cb] = pa;             \
                    uint2 pb = make_uint2(f2tf(XB(vb[j])), f2tf(XB(vb[j+4])));\
                    *(uint2*)&Bs[bf][r_nt * BKP + 4*j + cb] = pb;             \
                }                                                             \
            } else {                                                          \
                const int p = (kr_tn & 3) * 4 + (kr_tn >> 2);                 \
                _Pragma("unroll")                                             \
                for (int j = 0; j < 8; j++) {                                 \
                    As[bf][(mc_tn + j) * BKP + p] = f2tf(va[j]);              \
                    Bs[bf][(mc_tn + j) * BKP + p] = f2tf(vb[j]);              \
                }                                                             \
            }                                                                 \
        }

    #define COMPUTE(bf)                                                      \
        {                                                                     \
            uint32_t bfr[4][4];                                               \
            _Pragma("unroll")                                                 \
            for (int j = 0; j < 4; j++)                                       \
                *(uint4*)bfr[j] = *(const uint4*)&Bs[bf][(wn + j * 8 + g) * BKP + 4 * t]; \
            _Pragma("unroll")                                                 \
            for (int i = 0; i < 4; i++) {                                     \
                uint32_t a0[4], a1[4];                                        \
                *(uint4*)a0 = *(const uint4*)&As[bf][(wm + i * 16 + g)     * BKP + 4 * t]; \
                *(uint4*)a1 = *(const uint4*)&As[bf][(wm + i * 16 + 8 + g) * BKP + 4 * t]; \
                _Pragma("unroll")                                             \
                for (int j = 0; j < 4; j++) {                                 \
                    MMA8(c[i][j], a0[0], a1[0], a0[1], a1[1], bfr[j][0], bfr[j][1]); \
                    MMA8(c[i][j], a0[2], a1[2], a0[3], a1[3], bfr[j][2], bfr[j][3]); \
                }                                                             \
            }                                                                 \
        }

    const int Kt = (LAYOUT == 0) ? K : ((K + 15) & ~15);

    FETCH(0); STAGE(0); __syncthreads();
    int buf = 0;
    #pragma unroll 1
    for (int k0 = 16; k0 < Kt; k0 += 16) {
        FETCH(k0);
        COMPUTE(buf);
        STAGE(buf ^ 1);
        __syncthreads();
        buf ^= 1;
    }
    COMPUTE(buf);

    #undef FETCH
    #undef STAGE
    #undef COMPUTE
    #undef XB

    // Epilogue
    const float scale = rsqrtf(321.0f);
    #pragma unroll
    for (int i = 0; i < 4; i++) {
        #pragma unroll
        for (int h = 0; h < 2; h++) {
            const int gm = m0 + wm + i * 16 + g + h * 8;
            if (gm >= M) continue;
            const float rn = (EPI == 2) ? rown[gm] : 0.f;
            #pragma unroll
            for (int j = 0; j < 4; j++) {
                const int gn = n0 + wn + j * 8 + 2 * t;
                float v0 = c[i][j][h * 2 + 0];
                float v1 = c[i][j][h * 2 + 1];
                if (EPI <= 1 && bias) {
                    if (gn     < N) v0 += bias[gn];
                    if (gn + 1 < N) v1 += bias[gn + 1];
                }
                if (EPI == 1) {
                    v0 = 0.5f * v0 * (1.f + erff(v0 * 0.70710678118654752f));
                    v1 = 0.5f * v1 * (1.f + erff(v1 * 0.70710678118654752f));
                }
                if (EPI == 2) {
                    float cn0 = (gn     < N) ? coln[gn]     : 0.f;
                    float cn1 = (gn + 1 < N) ? coln[gn + 1] : 0.f;
                    float w0 = sqrtf(fmaxf(rn * cn0 - v0 * v0, 0.f) + 1e-8f);
                    float w1 = sqrtf(fmaxf(rn * cn1 - v1 * v1, 0.f) + 1e-8f);
                    v0 = (0.7f * v0 + 0.3f * w0) * scale;
                    v1 = (0.7f * v1 + 0.3f * w1) * scale;
                }
                float* p = C + (size_t)gm * ldc + gn;
                if (gn + 1 < N)      *(float2*)p = make_float2(v0, v1);
                else if (gn < N)     *p = v0;
            }
        }
    }
}

__global__ void __launch_bounds__(256, 2) k_mma(
    const float* __restrict__ A, const float* __restrict__ B,
    const float* __restrict__ bias, float* __restrict__ C, int M, int N, int K)
{
    mma_tile<0, 0>(A, B, bias, C, M, N, K, K, K, N, nullptr, nullptr);
}
__global__ void __launch_bounds__(256, 2) k_mma_gelu(
    const float* __restrict__ A, const float* __restrict__ B,
    const float* __restrict__ bias, float* __restrict__ C, int M, int N, int K)
{
    mma_tile<0, 1>(A, B, bias, C, M, N, K, K, K, N, nullptr, nullptr);
}

// Fused Q/K/V projection (blockIdx.z selects the projection)
__global__ void __launch_bounds__(256, 2) k_qkv(
    const float* __restrict__ coeffs,
    const float* __restrict__ Wq, const float* __restrict__ Wk, const float* __restrict__ Wv,
    const float* __restrict__ bq, const float* __restrict__ bk, const float* __restrict__ bv,
    float* __restrict__ q, float* __restrict__ k, float* __restrict__ v)
{
    const float* W; const float* bi; float* out;
    if (blockIdx.z == 0)      { W = Wq; bi = bq; out = q; }
    else if (blockIdx.z == 1) { W = Wk; bi = bk; out = k; }
    else                      { W = Wv; bi = bv; out = v; }
    mma_tile<0, 0>(coeffs, W, bi, out, BN * 4, DD, DD, DD, DD, DD, nullptr, nullptr);
}

// dot + geometric score, batched over z = b*4 + head (TN over channels)
__global__ void __launch_bounds__(256, 2) k_dot_geom(
    const float* __restrict__ q, const float* __restrict__ k,
    const float* __restrict__ qn2, const float* __restrict__ kn2,
    float* __restrict__ sc)
{
    const int z = blockIdx.z;
    const int b = z >> 2, m = z & 3;
    const float* A  = q + (size_t)b * NCH * 2048 + m * 512;
    const float* Bm = k + (size_t)b * NCH * 2048 + m * 512;
    float* C = sc + (size_t)z * DD * DD;
    mma_tile<1, 2>(A, Bm, nullptr, C, DD, DD, NCH, 2048, 2048, DD,
                   qn2 + z * DD, kn2 + z * DD);
}

// attn out: C[d, l] = sum_s V[d,s] * P[l,s]; softmax applied on the fly to P
__global__ void __launch_bounds__(256, 2) k_av(
    const float* __restrict__ v, const float* __restrict__ pr,
    const float* __restrict__ smax, const float* __restrict__ sinv,
    float* __restrict__ attn)
{
    const int z = blockIdx.z;
    const int b = z >> 2, m = z & 3;
    const float* A  = v  + (size_t)b * NCH * 2048 + m * 512;
    const float* Bm = pr + (size_t)z * DD * DD;
    float* C = attn + (size_t)b * NCH * 2048 + m * 512;
    mma_tile<0, 0, true>(A, Bm, nullptr, C, NCH, DD, DD, 2048, DD, 2048,
                         nullptr, nullptr, smax + (size_t)z * DD, sinv + (size_t)z * DD);
}

// Per-row max and 1/sum(exp) over 512 score columns (one warp per row)
__global__ void __launch_bounds__(256) k_rowstats(
    const float* __restrict__ sc, float* __restrict__ smax, float* __restrict__ sinv)
{
    const int row  = blockIdx.x * 8 + (threadIdx.x >> 5);
    const int lane = threadIdx.x & 31;
    const float* p = sc + (size_t)row * DD;
    float v[16];
    float mx = -1e30f;
    #pragma unroll
    for (int i = 0; i < 16; i++) { v[i] = p[lane + 32 * i]; mx = fmaxf(mx, v[i]); }
    #pragma unroll
    for (int o = 16; o; o >>= 1) mx = fmaxf(mx, __shfl_xor_sync(0xffffffffu, mx, o));
    float s = 0.f;
    #pragma unroll
    for (int i = 0; i < 16; i++) s += expf(v[i] - mx);
    #pragma unroll
    for (int o = 16; o; o >>= 1) s += __shfl_xor_sync(0xffffffffu, s, o);
    if (lane == 0) { smax[row] = mx; sinv[row] = 1.f / s; }
}

// ---------------------------------------------------------------------------
// Input stats: means/stdev over S per (b, n)
// ---------------------------------------------------------------------------
__global__ void k_stats(const float* __restrict__ x,
                        float* __restrict__ means, float* __restrict__ stdev)
{
    const int b = blockIdx.x;
    const int n = blockIdx.y * 32 + threadIdx.x;
    float s = 0.f, s2 = 0.f;
    if (n < NCH) {
        for (int t = threadIdx.y; t < SS; t += 8) {
            float vv = x[((size_t)b * SS + t) * NCH + n];
            s += vv; s2 = fmaf(vv, vv, s2);
        }
    }
    __shared__ float sh[8][32], sh2[8][32];
    sh [threadIdx.y][threadIdx.x] = s;
    sh2[threadIdx.y][threadIdx.x] = s2;
    __syncthreads();
    if (threadIdx.y == 0 && n < NCH) {
        float a = 0.f, a2 = 0.f;
        #pragma unroll
        for (int i = 0; i < 8; i++) { a += sh[i][threadIdx.x]; a2 += sh2[i][threadIdx.x]; }
        float mu  = a * (1.f / SS);
        float var = a2 * (1.f / SS) - mu * mu;
        means[b * NCH + n] = mu;
        stdev[b * NCH + n] = sqrtf(var + 1e-5f);
    }
}

// Normalize + transpose: xn[b, n, s] = (x[b, s, n] - mu) / sd
__global__ void k_normT(const float* __restrict__ x,
                        const float* __restrict__ means, const float* __restrict__ stdev,
                        float* __restrict__ xn)
{
    __shared__ float tile[32][33];
    const int b  = blockIdx.z;
    const int s0 = blockIdx.x * 32;
    const int n0 = blockIdx.y * 32;
    #pragma unroll
    for (int r = 0; r < 4; r++) {
        int ss = s0 + threadIdx.y + r * 8;
        int nn = n0 + threadIdx.x;
        tile[threadIdx.y + r * 8][threadIdx.x] =
            (nn < NCH) ? x[((size_t)b * SS + ss) * NCH + nn] : 0.f;
    }
    __syncthreads();
    #pragma unroll
    for (int r = 0; r < 4; r++) {
        int nn = n0 + threadIdx.y + r * 8;
        int ss = s0 + threadIdx.x;
        if (nn < NCH) {
            float mu = means[b * NCH + nn];
            float sd = stdev[b * NCH + nn];
            xn[((size_t)b * NCH + nn) * SS + ss] =
                (tile[threadIdx.x][threadIdx.y + r * 8] - mu) / sd;
        }
    }
}

// ---------------------------------------------------------------------------
// SWT decomposition / reconstruction
// ---------------------------------------------------------------------------
__global__ void __launch_bounds__(512) k_swt_dec(
    const float* __restrict__ h, const float* __restrict__ h0,
    const float* __restrict__ h1, float* __restrict__ coeffs)
{
    const int bn = blockIdx.x;
    const int n  = bn % NCH;
    const int d  = threadIdx.x;
    __shared__ float buf[2][DD];
    buf[0][d] = h[(size_t)bn * DD + d];
    float f0[3], f1[3];
    #pragma unroll
    for (int kk = 0; kk < 3; kk++) { f0[kk] = h0[n * 3 + kk]; f1[kk] = h1[n * 3 + kk]; }
    __syncthreads();
    int cur = 0, dil = 1;
    const int pl[3] = {1, 1, 2};
    #pragma unroll
    for (int m = 0; m < 3; m++) {
        float det = 0.f, app = 0.f;
        #pragma unroll
        for (int kk = 0; kk < 3; kk++) {
            int idx = (d + kk * dil - pl[m] + DD) & (DD - 1);
            float vv = buf[cur][idx];
            det = fmaf(f1[kk], vv, det);
            app = fmaf(f0[kk], vv, app);
        }
        coeffs[((size_t)bn * 4 + (3 - m)) * DD + d] = det;
        buf[cur ^ 1][d] = app;
        __syncthreads();
        cur ^= 1; dil <<= 1;
    }
    coeffs[(size_t)bn * 4 * DD + d] = buf[cur][d];
}

__global__ void __launch_bounds__(512) k_swt_rec(
    const float* __restrict__ c, const float* __restrict__ g0,
    const float* __restrict__ g1, float* __restrict__ rec)
{
    const int bn = blockIdx.x;
    const int n  = bn % NCH;
    const int d  = threadIdx.x;
    __shared__ float app[2][DD];
    __shared__ float det[DD];
    app[0][d] = c[(size_t)bn * 4 * DD + d];
    float f0[3], f1[3];
    #pragma unroll
    for (int kk = 0; kk < 3; kk++) { f0[kk] = g0[n * 3 + kk]; f1[kk] = g1[n * 3 + kk]; }
    int cur = 0, dil = 4;
    const int pl[3] = {6, 3, 1};
    #pragma unroll
    for (int i = 0; i < 3; i++) {
        det[d] = c[((size_t)bn * 4 + 1 + i) * DD + d];
        __syncthreads();
        float acc = 0.f;
        #pragma unroll
        for (int kk = 0; kk < 3; kk++) {
            int idx = (d + kk * dil - pl[i] + DD) & (DD - 1);
            acc = fmaf(f0[kk], app[cur][idx], acc);
            acc = fmaf(f1[kk], det[idx], acc);
        }
        app[cur ^ 1][d] = 0.5f * acc;
        __syncthreads();
        cur ^= 1; dil >>= 1;
    }
    rec[(size_t)bn * DD + d] = app[cur][d];
}

// Row norms of Q and K over channels, per (b, head, l)
__global__ void __launch_bounds__(256) k_qknorms(
    const float* __restrict__ q, const float* __restrict__ k,
    float* __restrict__ qn2, float* __restrict__ kn2)
{
    const int z = blockIdx.y;
    const int b = z >> 2, m = z & 3;
    const int l = blockIdx.x * 256 + threadIdx.x;
    const size_t base = (size_t)b * NCH * 2048 + m * 512 + l;
    float sq = 0.f, sk = 0.f;
    for (int j = 0; j < NCH; j++) {
        float a = q[base + (size_t)j * 2048]; sq = fmaf(a, a, sq);
        float c = k[base + (size_t)j * 2048]; sk = fmaf(c, c, sk);
    }
    qn2[z * DD + l] = sq;
    kn2[z * DD + l] = sk;
}

// LayerNorm over D=512 (optionally fused residual add)
__global__ void __launch_bounds__(256) k_ln(
    const float* __restrict__ x, const float* __restrict__ res,
    const float* __restrict__ g, const float* __restrict__ bt,
    float* __restrict__ out)
{
    const size_t base = (size_t)blockIdx.x * DD;
    const int t = threadIdx.x;
    __shared__ float sh[8];
    float v0 = x[base + t], v1 = x[base + t + 256];
    if (res) { v0 += res[base + t]; v1 += res[base + t + 256]; }
    float s = blk_sum(v0 + v1, sh);
    float mu = s * (1.f / DD);
    float d0 = v0 - mu, d1 = v1 - mu;
    float vs = blk_sum(d0 * d0 + d1 * d1, sh);
    float rs = rsqrtf(vs * (1.f / DD) + 1e-5f);
    out[base + t]       = d0 * rs * g[t]       + bt[t];
    out[base + t + 256] = d1 * rs * g[t + 256] + bt[t + 256];
}

// dec output: out[b, p, n] = dec[b, n, p] * stdev[b, n] + means[b, n]
__global__ void k_dec_out(const float* __restrict__ dec,
                          const float* __restrict__ means, const float* __restrict__ stdev,
                          float* __restrict__ out)
{
    const int idx = blockIdx.x * 256 + threadIdx.x;
    if (idx >= BB * PP * NCH) return;
    const int n = idx % NCH;
    const int p = (idx / NCH) % PP;
    const int b = idx / (NCH * PP);
    out[idx] = dec[((size_t)b * NCH + n) * PP + p] * stdev[b * NCH + n] + means[b * NCH + n];
}

__global__ void k_tail(const float* __restrict__ means, const float* __restrict__ stdev,
                       float* __restrict__ out)
{
    const int i = blockIdx.x * 256 + threadIdx.x;
    if (i < BN) { out[i] = means[i]; out[BN + i] = stdev[i]; }
}

// ---------------------------------------------------------------------------
// Launch
// ---------------------------------------------------------------------------
extern "C" void kernel_launch(void* const* d_in, const int* in_sizes, int n_in,
                              void* d_out, int out_size)
{
    const float* x_enc  = (const float*)d_in[0];
    const float* emb_W  = (const float*)d_in[1];
    const float* emb_b  = (const float*)d_in[2];
    const float* h0     = (const float*)d_in[3];
    const float* h1     = (const float*)d_in[4];
    const float* g0     = (const float*)d_in[5];
    const float* g1     = (const float*)d_in[6];
    const float* Wq     = (const float*)d_in[7];
    const float* bq     = (const float*)d_in[8];
    const float* Wk     = (const float*)d_in[9];
    const float* bk     = (const float*)d_in[10];
    const float* Wv     = (const float*)d_in[11];
    const float* bv     = (const float*)d_in[12];
    const float* Wo     = (const float*)d_in[13];
    const float* bo     = (const float*)d_in[14];
    const float* W1     = (const float*)d_in[15];
    const float* b1     = (const float*)d_in[16];
    const float* W2     = (const float*)d_in[17];
    const float* b2     = (const float*)d_in[18];
    const float* ln1_g  = (const float*)d_in[19];
    const float* ln1_b  = (const float*)d_in[20];
    const float* ln2_g  = (const float*)d_in[21];
    const float* ln2_b  = (const float*)d_in[22];
    const float* lnf_g  = (const float*)d_in[23];
    const float* lnf_b  = (const float*)d_in[24];
    const float* proj_W = (const float*)d_in[25];
    const float* proj_b = (const float*)d_in[26];

    float *means, *stdev, *xn, *h, *coeffs, *q, *k, *v, *qn2, *kn2, *sc,
          *smaxb, *sinvb, *attn, *rec, *o, *x1, *y, *z, *hf, *dec;
    cudaGetSymbolAddress((void**)&means,  g_means);
    cudaGetSymbolAddress((void**)&stdev,  g_stdev);
    cudaGetSymbolAddress((void**)&xn,     g_xn);
    cudaGetSymbolAddress((void**)&h,      g_h);
    cudaGetSymbolAddress((void**)&coeffs, g_coeffs);
    cudaGetSymbolAddress((void**)&q,      g_q);
    cudaGetSymbolAddress((void**)&k,      g_k);
    cudaGetSymbolAddress((void**)&v,      g_v);
    cudaGetSymbolAddress((void**)&qn2,    g_qn2);
    cudaGetSymbolAddress((void**)&kn2,    g_kn2);
    cudaGetSymbolAddress((void**)&sc,     g_sc);
    cudaGetSymbolAddress((void**)&smaxb,  g_smax);
    cudaGetSymbolAddress((void**)&sinvb,  g_sinv);
    cudaGetSymbolAddress((void**)&attn,   g_attn);
    cudaGetSymbolAddress((void**)&rec,    g_rec);
    cudaGetSymbolAddress((void**)&o,      g_o);
    cudaGetSymbolAddress((void**)&x1,     g_x1);
    cudaGetSymbolAddress((void**)&y,      g_y);
    cudaGetSymbolAddress((void**)&z,      g_z);
    cudaGetSymbolAddress((void**)&hf,     g_hf);
    cudaGetSymbolAddress((void**)&dec,    g_dec);

    // Input stats + normalized transpose
    k_stats<<<dim3(BB, (NCH + 31) / 32), dim3(32, 8)>>>(x_enc, means, stdev);
    k_normT<<<dim3(SS / 32, (NCH + 31) / 32, BB), dim3(32, 8)>>>(x_enc, means, stdev, xn);

    // Embedding: h[bn, d] = xn[bn, :] . emb_W[d, :]
    k_mma<<<dim3(DD / 128, (BN + 127) / 128), 256>>>(xn, emb_W, emb_b, h, BN, DD, SS);

    const dim3 gQKV(DD / 128, (BN * 4 + 127) / 128, 3);
    const dim3 gD  (DD / 128, (BN + 127) / 128);

    for (int l = 0; l < 2; l++) {
        const float* h0l = h0 + (size_t)l * NCH * 3;
        const float* h1l = h1 + (size_t)l * NCH * 3;
        const float* g0l = g0 + (size_t)l * NCH * 3;
        const float* g1l = g1 + (size_t)l * NCH * 3;

        k_swt_dec<<<BN, DD>>>(h, h0l, h1l, coeffs);

        k_qkv<<<gQKV, 256>>>(coeffs,
                             Wq + (size_t)l * DD * DD, Wk + (size_t)l * DD * DD,
                             Wv + (size_t)l * DD * DD,
                             bq + l * DD, bk + l * DD, bv + l * DD, q, k, v);

        k_qknorms<<<dim3(2, BB * 4), 256>>>(q, k, qn2, kn2);
        k_dot_geom<<<dim3(4, 4, BB * 4), 256>>>(q, k, qn2, kn2, sc);
        k_rowstats<<<BB * 4 * DD / 8, 256>>>(sc, smaxb, sinvb);
        k_av<<<dim3(4, (NCH + 127) / 128, BB * 4), 256>>>(v, sc, smaxb, sinvb, attn);

        k_swt_rec<<<BN, DD>>>(attn, g0l, g1l, rec);

        k_mma<<<gD, 256>>>(rec, Wo + (size_t)l * DD * DD, bo + l * DD, o, BN, DD, DD);
        k_ln<<<BN, 256>>>(h, o, ln1_g + l * DD, ln1_b + l * DD, x1);

        k_mma_gelu<<<dim3(DFF / 128, (BN + 127) / 128), 256>>>(
            x1, W1 + (size_t)l * DFF * DD, b1 + l * DFF, y, BN, DFF, DD);
        k_mma<<<gD, 256>>>(y, W2 + (size_t)l * DD * DFF, b2 + l * DD, z, BN, DD, DFF);
        k_ln<<<BN, 256>>>(x1, z, ln2_g + l * DD, ln2_b + l * DD, h);
    }

    // Final LN + projection + de-normalization
    k_ln<<<BN, 256>>>(h, nullptr, lnf_g, lnf_b, hf);
    k_mma<<<dim3((PP + 127) / 128, (BN + 127) / 128), 256>>>(hf, proj_W, proj_b, dec, BN, PP, DD);
    k_dec_out<<<(BB * PP * NCH + 255) / 256, 256>>>(dec, means, stdev, (float*)d_out);

    // Tuple tail: (dec, means, stdev) flattened
    if (out_size >= BB * PP * NCH + 2 * BN)
        k_tail<<<(BN + 255) / 256, 256>>>(means, stdev, (float*)d_out + BB * PP * NCH);
}

// round 16
// speedup vs baseline: 1.5753x; 1.2383x over previous
#include <cuda_runtime.h>
#include <math.h>
#include <stdint.h>

// Problem constants
#define BB   16
#define SS   512
#define NCH  321
#define DD   512
#define DFF  2048
#define PP   96
#define BN   (BB*NCH)          // 5136 tokens

// ---------------------------------------------------------------------------
// Scratch buffers
// ---------------------------------------------------------------------------
__device__ float g_means[BN];
__device__ float g_stdev[BN];
__device__ float g_xn    [(size_t)BN*SS];
__device__ float g_h     [(size_t)BN*DD];
__device__ float g_coeffs[(size_t)BN*4*DD];
__device__ float g_q     [(size_t)BN*4*DD];
__device__ float g_k     [(size_t)BN*4*DD];
__device__ float g_v     [(size_t)BN*4*DD];
__device__ float g_qn2   [BB*4*DD];
__device__ float g_kn2   [BB*4*DD];
__device__ float g_sc    [(size_t)BB*4*DD*DD];   // 64 x 512 x 512
__device__ float g_smax  [BB*4*DD];
__device__ float g_sinv  [BB*4*DD];
__device__ float g_attn  [(size_t)BN*4*DD];
__device__ float g_rec   [(size_t)BN*DD];
__device__ float g_o     [(size_t)BN*DD];
__device__ float g_x1    [(size_t)BN*DD];
__device__ float g_y     [(size_t)BN*DFF];
__device__ float g_z     [(size_t)BN*DD];
__device__ float g_hf    [(size_t)BN*DD];
__device__ float g_dec   [(size_t)BN*PP];

// ---------------------------------------------------------------------------
// Helpers
// ---------------------------------------------------------------------------
__device__ __forceinline__ uint32_t f2tf(float x) {
    uint32_t r;
    asm("cvt.rna.tf32.f32 %0, %1;" : "=r"(r) : "f"(x));
    return r;
}

#define MMA8(cc, A0, A1, A2, A3, B0, B1)                                     \
    asm volatile("mma.sync.aligned.m16n8k8.row.col.f32.tf32.tf32.f32 "      \
        "{%0,%1,%2,%3}, {%4,%5,%6,%7}, {%8,%9}, {%0,%1,%2,%3};"             \
        : "+f"(cc[0]), "+f"(cc[1]), "+f"(cc[2]), "+f"(cc[3])                \
        : "r"(A0), "r"(A1), "r"(A2), "r"(A3), "r"(B0), "r"(B1))

// 4-word-granularity XOR swizzle: conflict-free for both the STS patterns
// and the 8-row fragment-read phases.
#define SWZ(row) ((((row) >> 1) & 3) << 2)

__device__ __forceinline__ float blk_sum(float v, float* sh) {
    #pragma unroll
    for (int o = 16; o; o >>= 1) v += __shfl_xor_sync(0xffffffffu, v, o);
    int t = threadIdx.x;
    if ((t & 31) == 0) sh[t >> 5] = v;
    __syncthreads();
    v = sh[0] + sh[1] + sh[2] + sh[3] + sh[4] + sh[5] + sh[6] + sh[7];
    __syncthreads();
    return v;
}

// ---------------------------------------------------------------------------
// TF32 tensor-core GEMM tile: 128x128 CTA, BK=16, 8 warps (2x4), warp 64x32.
// Single register prefetch, double smem buffer, XOR-swizzled smem (16 words
// per row, no padding). k-permuted: word o = (k&3)*4 + (k>>2), then
// o' = (o & ~3) ^ SWZ(row) + (o & 3).
// LAYOUT 0 (NT): C[m,n] = sum_k A[m*lda+k] * B[n*ldb+k]   (K % 16 == 0)
// LAYOUT 1 (TN): C[m,n] = sum_k A[k*lda+m] * B[k*ldb+n]   (arbitrary K)
// EPI 0: +bias    EPI 1: +bias, exact GELU    EPI 2: geometric wedge score
// SOFTB: B rows are attention scores; apply exp(x - smax[row]) * sinv[row]
// ---------------------------------------------------------------------------
template<int LAYOUT, int EPI, bool SOFTB = false>
__device__ __forceinline__ void mma_tile(
    const float* __restrict__ A, const float* __restrict__ Bm,
    const float* __restrict__ bias, float* __restrict__ C,
    int M, int N, int K, int lda, int ldb, int ldc,
    const float* __restrict__ rown, const float* __restrict__ coln,
    const float* __restrict__ smax = nullptr, const float* __restrict__ sinv = nullptr)
{
    __shared__ uint32_t As[2][128 * 16];
    __shared__ uint32_t Bs[2][128 * 16];

    const int tid  = threadIdx.x;
    const int lane = tid & 31;
    const int g    = lane >> 2;
    const int t    = lane & 3;
    const int wid  = tid >> 5;
    const int wm   = (wid >> 2) * 64;
    const int wn   = (wid & 3) * 32;
    const int m0   = blockIdx.y * 128;
    const int n0   = blockIdx.x * 128;

    float c[4][4][4];
    #pragma unroll
    for (int i = 0; i < 4; i++)
        #pragma unroll
        for (int j = 0; j < 4; j++)
            #pragma unroll
            for (int r = 0; r < 4; r++) c[i][j][r] = 0.f;

    // loader indices
    const int r_nt  = tid >> 1;          // 0..127
    const int kg_nt = (tid & 1) * 8;     // 0 or 8
    const int kr_tn = tid >> 4;          // 0..15 (k within stage)
    const int mc_tn = tid & 15;          // 0..15 (column lane)
    const bool aok_nt = (m0 + r_nt) < M;
    const bool bok_nt = (n0 + r_nt) < N;

    float mxv = 0.f, invv = 1.f;
    if (SOFTB) {
        const int rr = n0 + r_nt;
        if (rr < N) { mxv = smax[rr]; invv = sinv[rr]; }
    }
    #define XB(x) (SOFTB ? expf((x) - mxv) * invv : (x))

    float va[8], vb[8];

    #define FETCH(k0)                                                         \
        {                                                                     \
            _Pragma("unroll")                                                 \
            for (int j = 0; j < 8; j++) { va[j] = 0.f; vb[j] = 0.f; }         \
            if (LAYOUT == 0) {                                                \
                if (aok_nt) {                                                 \
                    const float4* p = (const float4*)(A + (size_t)(m0 + r_nt) * lda + (k0) + kg_nt); \
                    float4 x0 = p[0], x1 = p[1];                              \
                    va[0]=x0.x; va[1]=x0.y; va[2]=x0.z; va[3]=x0.w;           \
                    va[4]=x1.x; va[5]=x1.y; va[6]=x1.z; va[7]=x1.w;           \
                }                                                             \
                if (bok_nt) {                                                 \
                    const float4* p = (const float4*)(Bm + (size_t)(n0 + r_nt) * ldb + (k0) + kg_nt); \
                    float4 x0 = p[0], x1 = p[1];                              \
                    vb[0]=x0.x; vb[1]=x0.y; vb[2]=x0.z; vb[3]=x0.w;           \
                    vb[4]=x1.x; vb[5]=x1.y; vb[6]=x1.z; vb[7]=x1.w;           \
                }                                                             \
            } else {                                                          \
                const int gk = (k0) + kr_tn;                                  \
                if (gk < K) {                                                 \
                    const float* pa = A  + (size_t)gk * lda + m0 + mc_tn;     \
                    const float* pb = Bm + (size_t)gk * ldb + n0 + mc_tn;     \
                    _Pragma("unroll")                                         \
                    for (int j = 0; j < 8; j++) {                             \
                        if (m0 + mc_tn + 16*j < M) va[j] = pa[16*j];          \
                        if (n0 + mc_tn + 16*j < N) vb[j] = pb[16*j];          \
                    }                                                         \
                }                                                             \
            }                                                                 \
        }

    #define STAGE(bf)                                                        \
        {                                                                     \
            if (LAYOUT == 0) {                                                \
                const int cb = kg_nt >> 2;      /* 0 or 2 */                  \
                const int sw = SWZ(r_nt);                                     \
                _Pragma("unroll")                                             \
                for (int j = 0; j < 4; j++) {                                 \
                    const int w = r_nt * 16 + ((4*j) ^ sw) + cb;              \
                    uint2 pa = make_uint2(f2tf(va[j]), f2tf(va[j+4]));        \
                    *(uint2*)&As[bf][w] = pa;                                 \
                    uint2 pb = make_uint2(f2tf(XB(vb[j])), f2tf(XB(vb[j+4])));\
                    *(uint2*)&Bs[bf][w] = pb;                                 \
                }                                                             \
            } else {                                                          \
                const int ob = (kr_tn & 3) * 4;                               \
                const int ol = kr_tn >> 2;                                    \
                _Pragma("unroll")                                             \
                for (int j = 0; j < 8; j++) {                                 \
                    const int row = mc_tn + 16 * j;                           \
                    const int w = row * 16 + (ob ^ SWZ(row)) + ol;            \
                    As[bf][w] = f2tf(va[j]);                                  \
                    Bs[bf][w] = f2tf(vb[j]);                                  \
                }                                                             \
            }                                                                 \
        }

    #define COMPUTE(bf)                                                      \
        {                                                                     \
            uint32_t bfr[4][4];                                               \
            _Pragma("unroll")                                                 \
            for (int j = 0; j < 4; j++) {                                     \
                const int row = wn + j * 8 + g;                               \
                *(uint4*)bfr[j] = *(const uint4*)&Bs[bf][row * 16 + ((4*t) ^ SWZ(row))]; \
            }                                                                 \
            _Pragma("unroll")                                                 \
            for (int i = 0; i < 4; i++) {                                     \
                uint32_t a0[4], a1[4];                                        \
                const int ra = wm + i * 16 + g;                               \
                const int rb = ra + 8;                                        \
                *(uint4*)a0 = *(const uint4*)&As[bf][ra * 16 + ((4*t) ^ SWZ(ra))]; \
                *(uint4*)a1 = *(const uint4*)&As[bf][rb * 16 + ((4*t) ^ SWZ(rb))]; \
                _Pragma("unroll")                                             \
                for (int j = 0; j < 4; j++) {                                 \
                    MMA8(c[i][j], a0[0], a1[0], a0[1], a1[1], bfr[j][0], bfr[j][1]); \
                    MMA8(c[i][j], a0[2], a1[2], a0[3], a1[3], bfr[j][2], bfr[j][3]); \
                }                                                             \
            }                                                                 \
        }

    const int Kt = (LAYOUT == 0) ? K : ((K + 15) & ~15);

    FETCH(0); STAGE(0); __syncthreads();
    int buf = 0;
    #pragma unroll 1
    for (int k0 = 16; k0 < Kt; k0 += 16) {
        FETCH(k0);
        COMPUTE(buf);
        STAGE(buf ^ 1);
        __syncthreads();
        buf ^= 1;
    }
    COMPUTE(buf);

    #undef FETCH
    #undef STAGE
    #undef COMPUTE
    #undef XB

    // Epilogue
    const float scale = rsqrtf(321.0f);
    #pragma unroll
    for (int i = 0; i < 4; i++) {
        #pragma unroll
        for (int h = 0; h < 2; h++) {
            const int gm = m0 + wm + i * 16 + g + h * 8;
            if (gm >= M) continue;
            const float rn = (EPI == 2) ? rown[gm] : 0.f;
            #pragma unroll
            for (int j = 0; j < 4; j++) {
                const int gn = n0 + wn + j * 8 + 2 * t;
                float v0 = c[i][j][h * 2 + 0];
                float v1 = c[i][j][h * 2 + 1];
                if (EPI <= 1 && bias) {
                    if (gn     < N) v0 += bias[gn];
                    if (gn + 1 < N) v1 += bias[gn + 1];
                }
                if (EPI == 1) {
                    v0 = 0.5f * v0 * (1.f + erff(v0 * 0.70710678118654752f));
                    v1 = 0.5f * v1 * (1.f + erff(v1 * 0.70710678118654752f));
                }
                if (EPI == 2) {
                    float cn0 = (gn     < N) ? coln[gn]     : 0.f;
                    float cn1 = (gn + 1 < N) ? coln[gn + 1] : 0.f;
                    float w0 = sqrtf(fmaxf(rn * cn0 - v0 * v0, 0.f) + 1e-8f);
                    float w1 = sqrtf(fmaxf(rn * cn1 - v1 * v1, 0.f) + 1e-8f);
                    v0 = (0.7f * v0 + 0.3f * w0) * scale;
                    v1 = (0.7f * v1 + 0.3f * w1) * scale;
                }
                float* p = C + (size_t)gm * ldc + gn;
                if (gn + 1 < N)      *(float2*)p = make_float2(v0, v1);
                else if (gn < N)     *p = v0;
            }
        }
    }
}

__global__ void __launch_bounds__(256, 2) k_mma(
    const float* __restrict__ A, const float* __restrict__ B,
    const float* __restrict__ bias, float* __restrict__ C, int M, int N, int K)
{
    mma_tile<0, 0>(A, B, bias, C, M, N, K, K, K, N, nullptr, nullptr);
}
__global__ void __launch_bounds__(256, 2) k_mma_gelu(
    const float* __restrict__ A, const float* __restrict__ B,
    const float* __restrict__ bias, float* __restrict__ C, int M, int N, int K)
{
    mma_tile<0, 1>(A, B, bias, C, M, N, K, K, K, N, nullptr, nullptr);
}

// Fused Q/K/V projection (blockIdx.z selects the projection)
__global__ void __launch_bounds__(256, 2) k_qkv(
    const float* __restrict__ coeffs,
    const float* __restrict__ Wq, const float* __restrict__ Wk, const float* __restrict__ Wv,
    const float* __restrict__ bq, const float* __restrict__ bk, const float* __restrict__ bv,
    float* __restrict__ q, float* __restrict__ k, float* __restrict__ v)
{
    const float* W; const float* bi; float* out;
    if (blockIdx.z == 0)      { W = Wq; bi = bq; out = q; }
    else if (blockIdx.z == 1) { W = Wk; bi = bk; out = k; }
    else                      { W = Wv; bi = bv; out = v; }
    mma_tile<0, 0>(coeffs, W, bi, out, BN * 4, DD, DD, DD, DD, DD, nullptr, nullptr);
}

// dot + geometric score, batched over z = b*4 + head (TN over channels)
__global__ void __launch_bounds__(256, 2) k_dot_geom(
    const float* __restrict__ q, const float* __restrict__ k,
    const float* __restrict__ qn2, const float* __restrict__ kn2,
    float* __restrict__ sc)
{
    const int z = blockIdx.z;
    const int b = z >> 2, m = z & 3;
    const float* A  = q + (size_t)b * NCH * 2048 + m * 512;
    const float* Bm = k + (size_t)b * NCH * 2048 + m * 512;
    float* C = sc + (size_t)z * DD * DD;
    mma_tile<1, 2>(A, Bm, nullptr, C, DD, DD, NCH, 2048, 2048, DD,
                   qn2 + z * DD, kn2 + z * DD);
}

// attn out: C[d, l] = sum_s V[d,s] * P[l,s]; softmax applied on the fly to P
__global__ void __launch_bounds__(256, 2) k_av(
    const float* __restrict__ v, const float* __restrict__ pr,
    const float* __restrict__ smax, const float* __restrict__ sinv,
    float* __restrict__ attn)
{
    const int z = blockIdx.z;
    const int b = z >> 2, m = z & 3;
    const float* A  = v  + (size_t)b * NCH * 2048 + m * 512;
    const float* Bm = pr + (size_t)z * DD * DD;
    float* C = attn + (size_t)b * NCH * 2048 + m * 512;
    mma_tile<0, 0, true>(A, Bm, nullptr, C, NCH, DD, DD, 2048, DD, 2048,
                         nullptr, nullptr, smax + (size_t)z * DD, sinv + (size_t)z * DD);
}

// Per-row max and 1/sum(exp) over 512 score columns (one warp per row)
__global__ void __launch_bounds__(256) k_rowstats(
    const float* __restrict__ sc, float* __restrict__ smax, float* __restrict__ sinv)
{
    const int row  = blockIdx.x * 8 + (threadIdx.x >> 5);
    const int lane = threadIdx.x & 31;
    const float* p = sc + (size_t)row * DD;
    float v[16];
    float mx = -1e30f;
    #pragma unroll
    for (int i = 0; i < 16; i++) { v[i] = p[lane + 32 * i]; mx = fmaxf(mx, v[i]); }
    #pragma unroll
    for (int o = 16; o; o >>= 1) mx = fmaxf(mx, __shfl_xor_sync(0xffffffffu, mx, o));
    float s = 0.f;
    #pragma unroll
    for (int i = 0; i < 16; i++) s += expf(v[i] - mx);
    #pragma unroll
    for (int o = 16; o; o >>= 1) s += __shfl_xor_sync(0xffffffffu, s, o);
    if (lane == 0) { smax[row] = mx; sinv[row] = 1.f / s; }
}

// ---------------------------------------------------------------------------
// Input stats: means/stdev over S per (b, n)
// ---------------------------------------------------------------------------
__global__ void k_stats(const float* __restrict__ x,
                        float* __restrict__ means, float* __restrict__ stdev)
{
    const int b = blockIdx.x;
    const int n = blockIdx.y * 32 + threadIdx.x;
    float s = 0.f, s2 = 0.f;
    if (n < NCH) {
        for (int t = threadIdx.y; t < SS; t += 8) {
            float vv = x[((size_t)b * SS + t) * NCH + n];
            s += vv; s2 = fmaf(vv, vv, s2);
        }
    }
    __shared__ float sh[8][32], sh2[8][32];
    sh [threadIdx.y][threadIdx.x] = s;
    sh2[threadIdx.y][threadIdx.x] = s2;
    __syncthreads();
    if (threadIdx.y == 0 && n < NCH) {
        float a = 0.f, a2 = 0.f;
        #pragma unroll
        for (int i = 0; i < 8; i++) { a += sh[i][threadIdx.x]; a2 += sh2[i][threadIdx.x]; }
        float mu  = a * (1.f / SS);
        float var = a2 * (1.f / SS) - mu * mu;
        means[b * NCH + n] = mu;
        stdev[b * NCH + n] = sqrtf(var + 1e-5f);
    }
}

// Normalize + transpose: xn[b, n, s] = (x[b, s, n] - mu) / sd
__global__ void k_normT(const float* __restrict__ x,
                        const float* __restrict__ means, const float* __restrict__ stdev,
                        float* __restrict__ xn)
{
    __shared__ float tile[32][33];
    const int b  = blockIdx.z;
    const int s0 = blockIdx.x * 32;
    const int n0 = blockIdx.y * 32;
    #pragma unroll
    for (int r = 0; r < 4; r++) {
        int ss = s0 + threadIdx.y + r * 8;
        int nn = n0 + threadIdx.x;
        tile[threadIdx.y + r * 8][threadIdx.x] =
            (nn < NCH) ? x[((size_t)b * SS + ss) * NCH + nn] : 0.f;
    }
    __syncthreads();
    #pragma unroll
    for (int r = 0; r < 4; r++) {
        int nn = n0 + threadIdx.y + r * 8;
        int ss = s0 + threadIdx.x;
        if (nn < NCH) {
            float mu = means[b * NCH + nn];
            float sd = stdev[b * NCH + nn];
            xn[((size_t)b * NCH + nn) * SS + ss] =
                (tile[threadIdx.x][threadIdx.y + r * 8] - mu) / sd;
        }
    }
}

// ---------------------------------------------------------------------------
// SWT decomposition / reconstruction
// ---------------------------------------------------------------------------
__global__ void __launch_bounds__(512) k_swt_dec(
    const float* __restrict__ h, const float* __restrict__ h0,
    const float* __restrict__ h1, float* __restrict__ coeffs)
{
    const int bn = blockIdx.x;
    const int n  = bn % NCH;
    const int d  = threadIdx.x;
    __shared__ float buf[2][DD];
    buf[0][d] = h[(size_t)bn * DD + d];
    float f0[3], f1[3];
    #pragma unroll
    for (int kk = 0; kk < 3; kk++) { f0[kk] = h0[n * 3 + kk]; f1[kk] = h1[n * 3 + kk]; }
    __syncthreads();
    int cur = 0, dil = 1;
    const int pl[3] = {1, 1, 2};
    #pragma unroll
    for (int m = 0; m < 3; m++) {
        float det = 0.f, app = 0.f;
        #pragma unroll
        for (int kk = 0; kk < 3; kk++) {
            int idx = (d + kk * dil - pl[m] + DD) & (DD - 1);
            float vv = buf[cur][idx];
            det = fmaf(f1[kk], vv, det);
            app = fmaf(f0[kk], vv, app);
        }
        coeffs[((size_t)bn * 4 + (3 - m)) * DD + d] = det;
        buf[cur ^ 1][d] = app;
        __syncthreads();
        cur ^= 1; dil <<= 1;
    }
    coeffs[(size_t)bn * 4 * DD + d] = buf[cur][d];
}

__global__ void __launch_bounds__(512) k_swt_rec(
    const float* __restrict__ c, const float* __restrict__ g0,
    const float* __restrict__ g1, float* __restrict__ rec)
{
    const int bn = blockIdx.x;
    const int n  = bn % NCH;
    const int d  = threadIdx.x;
    __shared__ float app[2][DD];
    __shared__ float det[DD];
    app[0][d] = c[(size_t)bn * 4 * DD + d];
    float f0[3], f1[3];
    #pragma unroll
    for (int kk = 0; kk < 3; kk++) { f0[kk] = g0[n * 3 + kk]; f1[kk] = g1[n * 3 + kk]; }
    int cur = 0, dil = 4;
    const int pl[3] = {6, 3, 1};
    #pragma unroll
    for (int i = 0; i < 3; i++) {
        det[d] = c[((size_t)bn * 4 + 1 + i) * DD + d];
        __syncthreads();
        float acc = 0.f;
        #pragma unroll
        for (int kk = 0; kk < 3; kk++) {
            int idx = (d + kk * dil - pl[i] + DD) & (DD - 1);
            acc = fmaf(f0[kk], app[cur][idx], acc);
            acc = fmaf(f1[kk], det[idx], acc);
        }
        app[cur ^ 1][d] = 0.5f * acc;
        __syncthreads();
        cur ^= 1; dil >>= 1;
    }
    rec[(size_t)bn * DD + d] = app[cur][d];
}

// Row norms of Q and K over channels, per (b, head, l)
__global__ void __launch_bounds__(256) k_qknorms(
    const float* __restrict__ q, const float* __restrict__ k,
    float* __restrict__ qn2, float* __restrict__ kn2)
{
    const int z = blockIdx.y;
    const int b = z >> 2, m = z & 3;
    const int l = blockIdx.x * 256 + threadIdx.x;
    const size_t base = (size_t)b * NCH * 2048 + m * 512 + l;
    float sq = 0.f, sk = 0.f;
    for (int j = 0; j < NCH; j++) {
        float a = q[base + (size_t)j * 2048]; sq = fmaf(a, a, sq);
        float c = k[base + (size_t)j * 2048]; sk = fmaf(c, c, sk);
    }
    qn2[z * DD + l] = sq;
    kn2[z * DD + l] = sk;
}

// LayerNorm over D=512 (optionally fused residual add)
__global__ void __launch_bounds__(256) k_ln(
    const float* __restrict__ x, const float* __restrict__ res,
    const float* __restrict__ g, const float* __restrict__ bt,
    float* __restrict__ out)
{
    const size_t base = (size_t)blockIdx.x * DD;
    const int t = threadIdx.x;
    __shared__ float sh[8];
    float v0 = x[base + t], v1 = x[base + t + 256];
    if (res) { v0 += res[base + t]; v1 += res[base + t + 256]; }
    float s = blk_sum(v0 + v1, sh);
    float mu = s * (1.f / DD);
    float d0 = v0 - mu, d1 = v1 - mu;
    float vs = blk_sum(d0 * d0 + d1 * d1, sh);
    float rs = rsqrtf(vs * (1.f / DD) + 1e-5f);
    out[base + t]       = d0 * rs * g[t]       + bt[t];
    out[base + t + 256] = d1 * rs * g[t + 256] + bt[t + 256];
}

// dec output: out[b, p, n] = dec[b, n, p] * stdev[b, n] + means[b, n]
__global__ void k_dec_out(const float* __restrict__ dec,
                          const float* __restrict__ means, const float* __restrict__ stdev,
                          float* __restrict__ out)
{
    const int idx = blockIdx.x * 256 + threadIdx.x;
    if (idx >= BB * PP * NCH) return;
    const int n = idx % NCH;
    const int p = (idx / NCH) % PP;
    const int b = idx / (NCH * PP);
    out[idx] = dec[((size_t)b * NCH + n) * PP + p] * stdev[b * NCH + n] + means[b * NCH + n];
}

__global__ void k_tail(const float* __restrict__ means, const float* __restrict__ stdev,
                       float* __restrict__ out)
{
    const int i = blockIdx.x * 256 + threadIdx.x;
    if (i < BN) { out[i] = means[i]; out[BN + i] = stdev[i]; }
}

// ---------------------------------------------------------------------------
// Launch
// ---------------------------------------------------------------------------
extern "C" void kernel_launch(void* const* d_in, const int* in_sizes, int n_in,
                              void* d_out, int out_size)
{
    const float* x_enc  = (const float*)d_in[0];
    const float* emb_W  = (const float*)d_in[1];
    const float* emb_b  = (const float*)d_in[2];
    const float* h0     = (const float*)d_in[3];
    const float* h1     = (const float*)d_in[4];
    const float* g0     = (const float*)d_in[5];
    const float* g1     = (const float*)d_in[6];
    const float* Wq     = (const float*)d_in[7];
    const float* bq     = (const float*)d_in[8];
    const float* Wk     = (const float*)d_in[9];
    const float* bk     = (const float*)d_in[10];
    const float* Wv     = (const float*)d_in[11];
    const float* bv     = (const float*)d_in[12];
    const float* Wo     = (const float*)d_in[13];
    const float* bo     = (const float*)d_in[14];
    const float* W1     = (const float*)d_in[15];
    const float* b1     = (const float*)d_in[16];
    const float* W2     = (const float*)d_in[17];
    const float* b2     = (const float*)d_in[18];
    const float* ln1_g  = (const float*)d_in[19];
    const float* ln1_b  = (const float*)d_in[20];
    const float* ln2_g  = (const float*)d_in[21];
    const float* ln2_b  = (const float*)d_in[22];
    const float* lnf_g  = (const float*)d_in[23];
    const float* lnf_b  = (const float*)d_in[24];
    const float* proj_W = (const float*)d_in[25];
    const float* proj_b = (const float*)d_in[26];

    float *means, *stdev, *xn, *h, *coeffs, *q, *k, *v, *qn2, *kn2, *sc,
          *smaxb, *sinvb, *attn, *rec, *o, *x1, *y, *z, *hf, *dec;
    cudaGetSymbolAddress((void**)&means,  g_means);
    cudaGetSymbolAddress((void**)&stdev,  g_stdev);
    cudaGetSymbolAddress((void**)&xn,     g_xn);
    cudaGetSymbolAddress((void**)&h,      g_h);
    cudaGetSymbolAddress((void**)&coeffs, g_coeffs);
    cudaGetSymbolAddress((void**)&q,      g_q);
    cudaGetSymbolAddress((void**)&k,      g_k);
    cudaGetSymbolAddress((void**)&v,      g_v);
    cudaGetSymbolAddress((void**)&qn2,    g_qn2);
    cudaGetSymbolAddress((void**)&kn2,    g_kn2);
    cudaGetSymbolAddress((void**)&sc,     g_sc);
    cudaGetSymbolAddress((void**)&smaxb,  g_smax);
    cudaGetSymbolAddress((void**)&sinvb,  g_sinv);
    cudaGetSymbolAddress((void**)&attn,   g_attn);
    cudaGetSymbolAddress((void**)&rec,    g_rec);
    cudaGetSymbolAddress((void**)&o,      g_o);
    cudaGetSymbolAddress((void**)&x1,     g_x1);
    cudaGetSymbolAddress((void**)&y,      g_y);
    cudaGetSymbolAddress((void**)&z,      g_z);
    cudaGetSymbolAddress((void**)&hf,     g_hf);
    cudaGetSymbolAddress((void**)&dec,    g_dec);

    // Input stats + normalized transpose
    k_stats<<<dim3(BB, (NCH + 31) / 32), dim3(32, 8)>>>(x_enc, means, stdev);
    k_normT<<<dim3(SS / 32, (NCH + 31) / 32, BB), dim3(32, 8)>>>(x_enc, means, stdev, xn);

    // Embedding: h[bn, d] = xn[bn, :] . emb_W[d, :]
    k_mma<<<dim3(DD / 128, (BN + 127) / 128), 256>>>(xn, emb_W, emb_b, h, BN, DD, SS);

    const dim3 gQKV(DD / 128, (BN * 4 + 127) / 128, 3);
    const dim3 gD  (DD / 128, (BN + 127) / 128);

    for (int l = 0; l < 2; l++) {
        const float* h0l = h0 + (size_t)l * NCH * 3;
        const float* h1l = h1 + (size_t)l * NCH * 3;
        const float* g0l = g0 + (size_t)l * NCH * 3;
        const float* g1l = g1 + (size_t)l * NCH * 3;

        k_swt_dec<<<BN, DD>>>(h, h0l, h1l, coeffs);

        k_qkv<<<gQKV, 256>>>(coeffs,
                             Wq + (size_t)l * DD * DD, Wk + (size_t)l * DD * DD,
                             Wv + (size_t)l * DD * DD,
                             bq + l * DD, bk + l * DD, bv + l * DD, q, k, v);

        k_qknorms<<<dim3(2, BB * 4), 256>>>(q, k, qn2, kn2);
        k_dot_geom<<<dim3(4, 4, BB * 4), 256>>>(q, k, qn2, kn2, sc);
        k_rowstats<<<BB * 4 * DD / 8, 256>>>(sc, smaxb, sinvb);
        k_av<<<dim3(4, (NCH + 127) / 128, BB * 4), 256>>>(v, sc, smaxb, sinvb, attn);

        k_swt_rec<<<BN, DD>>>(attn, g0l, g1l, rec);

        k_mma<<<gD, 256>>>(rec, Wo + (size_t)l * DD * DD, bo + l * DD, o, BN, DD, DD);
        k_ln<<<BN, 256>>>(h, o, ln1_g + l * DD, ln1_b + l * DD, x1);

        k_mma_gelu<<<dim3(DFF / 128, (BN + 127) / 128), 256>>>(
            x1, W1 + (size_t)l * DFF * DD, b1 + l * DFF, y, BN, DFF, DD);
        k_mma<<<gD, 256>>>(y, W2 + (size_t)l * DD * DFF, b2 + l * DD, z, BN, DD, DFF);
        k_ln<<<BN, 256>>>(x1, z, ln2_g + l * DD, ln2_b + l * DD, h);
    }

    // Final LN + projection + de-normalization
    k_ln<<<BN, 256>>>(h, nullptr, lnf_g, lnf_b, hf);
    k_mma<<<dim3((PP + 127) / 128, (BN + 127) / 128), 256>>>(hf, proj_W, proj_b, dec, BN, PP, DD);
    k_dec_out<<<(BB * PP * NCH + 255) / 256, 256>>>(dec, means, stdev, (float*)d_out);

    // Tuple tail: (dec, means, stdev) flattened
    if (out_size >= BB * PP * NCH + 2 * BN)
        k_tail<<<(BN + 255) / 256, 256>>>(means, stdev, (float*)d_out + BB * PP * NCH);
}